// round 1
// baseline (speedup 1.0000x reference)
#include <cuda_runtime.h>
#include <math.h>

#define Bsz 4
#define Tn  2048
#define Cn  1024
#define Hn  16
#define Dn  64

// Scratch (static device globals — no allocation allowed in kernel_launch)
__device__ float g_q[(size_t)Bsz * Hn * Tn * Dn];   // [B,H,T,D]
__device__ float g_k[(size_t)Bsz * Hn * Tn * Dn];
__device__ float g_v[(size_t)Bsz * Hn * Tn * Dn];
__device__ float g_o[(size_t)Bsz * Tn * Cn];        // [B,T,C] attention output

// ---------------------------------------------------------------------------
// Tiled GEMM: out[m][n] = sum_k A[m][k] * W[n][k] + bias[n]
// BM=BN=128, BK=16, 256 threads, 8x8 micro-tile.
// MODE 0: A = x, scatter result into g_q/g_k/g_v ([B,H,T,D] layout)
// MODE 1: A = g_o (device global), plain row-major output
// ---------------------------------------------------------------------------
template <int MODE>
__global__ __launch_bounds__(256, 2)
void gemm128(const float* __restrict__ A, const float* __restrict__ W,
             const float* __restrict__ bias, float* __restrict__ out, int Kdim)
{
    __shared__ float As[16 * 132];   // [k][m] transposed, padded
    __shared__ float Ws[16 * 132];   // [k][n] transposed, padded

    const int tid = threadIdx.x;
    const int tx = tid & 15;
    const int ty = tid >> 4;
    const int m0 = blockIdx.y * 128;
    const int n0 = blockIdx.x * 128;

    const float* Abase = (MODE == 1) ? g_o : A;

    const int lrow = tid >> 1;          // 0..127
    const int lk4  = (tid & 1) * 8;     // 0 or 8

    const float* Ap = Abase + (size_t)(m0 + lrow) * Kdim + lk4;
    const float* Wp = W     + (size_t)(n0 + lrow) * Kdim + lk4;

    float acc[8][8];
#pragma unroll
    for (int i = 0; i < 8; i++)
#pragma unroll
        for (int j = 0; j < 8; j++) acc[i][j] = 0.f;

    for (int k0 = 0; k0 < Kdim; k0 += 16) {
        float4 a0 = *(const float4*)(Ap + k0);
        float4 a1 = *(const float4*)(Ap + k0 + 4);
        float4 w0 = *(const float4*)(Wp + k0);
        float4 w1 = *(const float4*)(Wp + k0 + 4);
        __syncthreads();
        As[(lk4 + 0) * 132 + lrow] = a0.x;
        As[(lk4 + 1) * 132 + lrow] = a0.y;
        As[(lk4 + 2) * 132 + lrow] = a0.z;
        As[(lk4 + 3) * 132 + lrow] = a0.w;
        As[(lk4 + 4) * 132 + lrow] = a1.x;
        As[(lk4 + 5) * 132 + lrow] = a1.y;
        As[(lk4 + 6) * 132 + lrow] = a1.z;
        As[(lk4 + 7) * 132 + lrow] = a1.w;
        Ws[(lk4 + 0) * 132 + lrow] = w0.x;
        Ws[(lk4 + 1) * 132 + lrow] = w0.y;
        Ws[(lk4 + 2) * 132 + lrow] = w0.z;
        Ws[(lk4 + 3) * 132 + lrow] = w0.w;
        Ws[(lk4 + 4) * 132 + lrow] = w1.x;
        Ws[(lk4 + 5) * 132 + lrow] = w1.y;
        Ws[(lk4 + 6) * 132 + lrow] = w1.z;
        Ws[(lk4 + 7) * 132 + lrow] = w1.w;
        __syncthreads();

#pragma unroll
        for (int kk = 0; kk < 16; kk++) {
            float4 av0 = *(const float4*)&As[kk * 132 + ty * 8];
            float4 av1 = *(const float4*)&As[kk * 132 + ty * 8 + 4];
            float4 wv0 = *(const float4*)&Ws[kk * 132 + tx * 8];
            float4 wv1 = *(const float4*)&Ws[kk * 132 + tx * 8 + 4];
            float a[8] = {av0.x, av0.y, av0.z, av0.w, av1.x, av1.y, av1.z, av1.w};
            float w[8] = {wv0.x, wv0.y, wv0.z, wv0.w, wv1.x, wv1.y, wv1.z, wv1.w};
#pragma unroll
            for (int i = 0; i < 8; i++)
#pragma unroll
                for (int j = 0; j < 8; j++)
                    acc[i][j] += a[i] * w[j];
        }
    }

    // epilogue
    if (MODE == 0) {
#pragma unroll
        for (int i = 0; i < 8; i++) {
            int m = m0 + ty * 8 + i;
            int bb = m >> 11;          // / 2048
            int t  = m & 2047;
#pragma unroll
            for (int j = 0; j < 8; j++) {
                int f = n0 + tx * 8 + j;
                float val = acc[i][j] + bias[f];
                int which = f >> 10;   // 0=q 1=k 2=v
                int fc = f & 1023;
                int hh = fc >> 6;
                int d  = fc & 63;
                float* dst = (which == 0) ? g_q : (which == 1) ? g_k : g_v;
                dst[(((size_t)bb * Hn + hh) * Tn + t) * Dn + d] = val;
            }
        }
    } else {
#pragma unroll
        for (int i = 0; i < 8; i++) {
            int m = m0 + ty * 8 + i;
            float* op = out + (size_t)m * 1024 + n0 + tx * 8;
            float4 r0 = make_float4(acc[i][0] + bias[n0 + tx * 8 + 0],
                                    acc[i][1] + bias[n0 + tx * 8 + 1],
                                    acc[i][2] + bias[n0 + tx * 8 + 2],
                                    acc[i][3] + bias[n0 + tx * 8 + 3]);
            float4 r1 = make_float4(acc[i][4] + bias[n0 + tx * 8 + 4],
                                    acc[i][5] + bias[n0 + tx * 8 + 5],
                                    acc[i][6] + bias[n0 + tx * 8 + 6],
                                    acc[i][7] + bias[n0 + tx * 8 + 7]);
            *(float4*)(op)     = r0;
            *(float4*)(op + 4) = r1;
        }
    }
}

// ---------------------------------------------------------------------------
// Flash attention with additive bias. Br=Bc=128, D=64, 256 threads.
// grid: (T/128, H, B)
// ---------------------------------------------------------------------------
#define ATTN_SMEM_FLOATS (64*132 + 64*132 + 128*64 + 128*132 + 3*128)
#define ATTN_SMEM_BYTES  (ATTN_SMEM_FLOATS * 4)

__global__ __launch_bounds__(256, 1)
void attn_kernel(const float* __restrict__ bias)
{
    extern __shared__ float sm[];
    float* Qt  = sm;                    // [d][r]  64 x 132 (Q * 1/8)
    float* Kt  = Qt + 64 * 132;         // [d][c]  64 x 132
    float* Vs  = Kt + 64 * 132;         // [c][d]  128 x 64
    float* Ps  = Vs + 128 * 64;         // [r][c]  128 x 132
    float* m_s = Ps + 128 * 132;        // 128
    float* l_s = m_s + 128;             // 128
    float* al_s = l_s + 128;            // 128

    const int tid = threadIdx.x;
    const int tx = tid & 15;
    const int ty = tid >> 4;
    const int qt = blockIdx.x;          // 0..15
    const int h  = blockIdx.y;
    const int b  = blockIdx.z;

    const size_t headoff = ((size_t)(b * Hn + h)) * Tn * Dn;
    const float* qg = g_q + headoff + (size_t)qt * 128 * Dn;
    const float* kg = g_k + headoff;
    const float* vg = g_v + headoff;

    // Load Q tile transposed, pre-scaled by 1/sqrt(D) = 1/8
    {
        int r  = tid & 127;
        int dv = tid >> 7;   // 0/1
#pragma unroll
        for (int p = 0; p < 8; p++) {
            int d0 = (p * 2 + dv) * 4;
            float4 q4 = *(const float4*)(qg + r * 64 + d0);
            Qt[(d0 + 0) * 132 + r] = q4.x * 0.125f;
            Qt[(d0 + 1) * 132 + r] = q4.y * 0.125f;
            Qt[(d0 + 2) * 132 + r] = q4.z * 0.125f;
            Qt[(d0 + 3) * 132 + r] = q4.w * 0.125f;
        }
    }
    if (tid < 128) { m_s[tid] = -INFINITY; l_s[tid] = 0.f; }

    float o[8][4];
#pragma unroll
    for (int i = 0; i < 8; i++)
#pragma unroll
        for (int j = 0; j < 4; j++) o[i][j] = 0.f;

    for (int kt = 0; kt < 16; kt++) {
        __syncthreads();
        // load K tile transposed
        {
            int r  = tid & 127;
            int dv = tid >> 7;
            const float* kp = kg + (size_t)(kt * 128 + r) * 64;
#pragma unroll
            for (int p = 0; p < 8; p++) {
                int d0 = (p * 2 + dv) * 4;
                float4 k4 = *(const float4*)(kp + d0);
                Kt[(d0 + 0) * 132 + r] = k4.x;
                Kt[(d0 + 1) * 132 + r] = k4.y;
                Kt[(d0 + 2) * 132 + r] = k4.z;
                Kt[(d0 + 3) * 132 + r] = k4.w;
            }
        }
        // load V tile (natural layout)
        {
            int rr = tid >> 4;
            int dd = (tid & 15) * 4;
            const float* vp = vg + (size_t)kt * 128 * 64;
#pragma unroll
            for (int p = 0; p < 8; p++) {
                int row = p * 16 + rr;
                *(float4*)&Vs[row * 64 + dd] = *(const float4*)(vp + row * 64 + dd);
            }
        }
        __syncthreads();

        // S = (Q/8) @ K^T  (8x8 micro-tile)
        float s[8][8];
#pragma unroll
        for (int i = 0; i < 8; i++)
#pragma unroll
            for (int j = 0; j < 8; j++) s[i][j] = 0.f;

        for (int d = 0; d < 64; d++) {
            float4 a0 = *(const float4*)&Qt[d * 132 + ty * 8];
            float4 a1 = *(const float4*)&Qt[d * 132 + ty * 8 + 4];
            float4 b0 = *(const float4*)&Kt[d * 132 + tx * 8];
            float4 b1 = *(const float4*)&Kt[d * 132 + tx * 8 + 4];
            float a[8] = {a0.x, a0.y, a0.z, a0.w, a1.x, a1.y, a1.z, a1.w};
            float w[8] = {b0.x, b0.y, b0.z, b0.w, b1.x, b1.y, b1.z, b1.w};
#pragma unroll
            for (int i = 0; i < 8; i++)
#pragma unroll
                for (int j = 0; j < 8; j++)
                    s[i][j] += a[i] * w[j];
        }

        // add bias, store S to smem (row-major)
        const float* bp = bias + ((size_t)b * Tn + qt * 128) * Tn + (size_t)kt * 128;
#pragma unroll
        for (int i = 0; i < 8; i++) {
            int r = ty * 8 + i;
            float4 b40 = *(const float4*)(bp + (size_t)r * Tn + tx * 8);
            float4 b41 = *(const float4*)(bp + (size_t)r * Tn + tx * 8 + 4);
            float4 p0 = make_float4(s[i][0] + b40.x, s[i][1] + b40.y,
                                    s[i][2] + b40.z, s[i][3] + b40.w);
            float4 p1 = make_float4(s[i][4] + b41.x, s[i][5] + b41.y,
                                    s[i][6] + b41.z, s[i][7] + b41.w);
            *(float4*)&Ps[r * 132 + tx * 8]     = p0;
            *(float4*)&Ps[r * 132 + tx * 8 + 4] = p1;
        }
        __syncthreads();

        // pass A: per-row max, alpha, l prescale
        if (tid < 128) {
            float mold = m_s[tid];
            float mnew = mold;
            const float* pr = Ps + tid * 132;
#pragma unroll 16
            for (int c = 0; c < 128; c++) mnew = fmaxf(mnew, pr[c]);
            float alpha = __expf(mold - mnew);
            m_s[tid]  = mnew;
            al_s[tid] = alpha;
            l_s[tid] *= alpha;
        }
        __syncthreads();

        // rescale O accumulators
#pragma unroll
        for (int i = 0; i < 8; i++) {
            float a = al_s[ty * 8 + i];
#pragma unroll
            for (int j = 0; j < 4; j++) o[i][j] *= a;
        }

        // pass B: exponentiate + row sums (2 threads per row)
        {
            int r  = tid >> 1;
            int cb = (tid & 1) * 64;
            float mr = m_s[r];
            float* pr = Ps + r * 132 + cb;
            float psum = 0.f;
#pragma unroll 16
            for (int k = 0; k < 64; k++) {
                float p = __expf(pr[k] - mr);
                pr[k] = p;
                psum += p;
            }
            psum += __shfl_xor_sync(0xffffffffu, psum, 1);
            if ((tid & 1) == 0) l_s[r] += psum;
        }
        __syncthreads();

        // O += P @ V  (8 rows x 4 d-cols per thread)
        for (int c = 0; c < 128; c++) {
            float4 v4 = *(const float4*)&Vs[c * 64 + tx * 4];
#pragma unroll
            for (int i = 0; i < 8; i++) {
                float p = Ps[(ty * 8 + i) * 132 + c];
                o[i][0] += p * v4.x;
                o[i][1] += p * v4.y;
                o[i][2] += p * v4.z;
                o[i][3] += p * v4.w;
            }
        }
    }

    // epilogue: normalize and write to g_o in [B,T,C] layout
    float* og = g_o + ((size_t)b * Tn + (size_t)qt * 128) * Cn + h * Dn;
#pragma unroll
    for (int i = 0; i < 8; i++) {
        int r = ty * 8 + i;
        float inv = 1.0f / l_s[r];
        float4 o4 = make_float4(o[i][0] * inv, o[i][1] * inv,
                                o[i][2] * inv, o[i][3] * inv);
        *(float4*)(og + (size_t)r * Cn + tx * 4) = o4;
    }
}

// ---------------------------------------------------------------------------
extern "C" void kernel_launch(void* const* d_in, const int* in_sizes, int n_in,
                              void* d_out, int out_size)
{
    const float* x         = (const float*)d_in[0];
    const float* attn_bias = (const float*)d_in[1];
    const float* qkv_w     = (const float*)d_in[2];
    const float* qkv_b     = (const float*)d_in[3];
    const float* out_w     = (const float*)d_in[4];
    const float* out_b     = (const float*)d_in[5];
    float* out = (float*)d_out;
    (void)in_sizes; (void)n_in; (void)out_size;

    // QKV projection: [8192,1024] @ [3072,1024]^T -> scatter into q/k/v
    gemm128<0><<<dim3(3072 / 128, 8192 / 128), 256>>>(x, qkv_w, qkv_b, nullptr, 1024);

    // Attention (flash, online softmax, additive bias)
    cudaFuncSetAttribute(attn_kernel, cudaFuncAttributeMaxDynamicSharedMemorySize,
                         ATTN_SMEM_BYTES);
    attn_kernel<<<dim3(Tn / 128, Hn, Bsz), 256, ATTN_SMEM_BYTES>>>(attn_bias);

    // Output projection: [8192,1024] @ [1024,1024]^T
    gemm128<1><<<dim3(1024 / 128, 8192 / 128), 256>>>(nullptr, out_w, out_b, out, 1024);
}

// round 3
// speedup vs baseline: 1.3591x; 1.3591x over previous
#include <cuda_runtime.h>
#include <math.h>
#include <stdint.h>

#define Bsz 4
#define Tn  2048
#define Cn  1024
#define Hn  16
#define Dn  64

// Scratch (static device globals — no allocation allowed)
__device__ float g_q[(size_t)Bsz * Hn * Tn * Dn];   // [B,H,T,D]
__device__ float g_k[(size_t)Bsz * Hn * Tn * Dn];
__device__ float g_v[(size_t)Bsz * Hn * Tn * Dn];
__device__ float g_o[(size_t)Bsz * Tn * Cn];        // [B,T,C]

// ---------------------------------------------------------------------------
// helpers
// ---------------------------------------------------------------------------
__device__ __forceinline__ uint32_t smem_u32(const void* p) {
    uint32_t a;
    asm("{ .reg .u64 t; cvta.to.shared.u64 t, %1; cvt.u32.u64 %0, t; }"
        : "=r"(a) : "l"(p));
    return a;
}

__device__ __forceinline__ void cpa16(uint32_t s, const void* g) {
    asm volatile("cp.async.cg.shared.global [%0], [%1], 16;"
                 :: "r"(s), "l"(g) : "memory");
}

__device__ __forceinline__ uint32_t f2tf32(float f) {
    uint32_t r;
    asm("cvt.rna.tf32.f32 %0, %1;" : "=r"(r) : "f"(f));
    return r;
}

// D += A(16x8) * B(8x8)^T, tf32, fp32 accum
__device__ __forceinline__ void mma_tf32(float* d, const uint32_t* a, const uint32_t* b) {
    asm volatile(
        "mma.sync.aligned.m16n8k8.row.col.f32.tf32.tf32.f32 "
        "{%0,%1,%2,%3}, {%4,%5,%6,%7}, {%8,%9}, {%0,%1,%2,%3};"
        : "+f"(d[0]), "+f"(d[1]), "+f"(d[2]), "+f"(d[3])
        : "r"(a[0]), "r"(a[1]), "r"(a[2]), "r"(a[3]), "r"(b[0]), "r"(b[1]));
}

// ---------------------------------------------------------------------------
// tf32 mma.sync GEMM: out[m][n] = sum_k A[m][k] * W[n][k] + bias[n]
// BM=BN=128, BK=32, K=1024, 256 threads (8 warps in 2x4), warp tile 64x32.
// MODE 0: A = x, scatter into g_q/g_k/g_v.  MODE 1: A = g_o, row-major out.
// ---------------------------------------------------------------------------
#define GPAD 36                         // padded row stride (floats)
#define STAGE_FLOATS (2 * 128 * GPAD)   // A tile + B tile
#define GEMM_SMEM_BYTES (2 * STAGE_FLOATS * 4)

template <int MODE>
__global__ __launch_bounds__(256, 1)
void gemm_mma(const float* __restrict__ A, const float* __restrict__ W,
              const float* __restrict__ bias, float* __restrict__ out)
{
    constexpr int KD  = 1024;
    constexpr int NKT = KD / 32;

    extern __shared__ float sm[];
    const uint32_t smb = smem_u32(sm);

    const int tid  = threadIdx.x;
    const int wid  = tid >> 5;
    const int lane = tid & 31;
    const int wm   = wid >> 2;          // 0..1
    const int wn   = wid & 3;           // 0..3
    const int lq   = lane >> 2;         // 0..7
    const int lr   = lane & 3;          // 0..3
    const int n0 = blockIdx.x * 128;
    const int m0 = blockIdx.y * 128;

    const float* Abase = (MODE == 1) ? g_o : A;

    // global load mapping: 2 threads per row, 4 float4 each for A and for W
    const int grow = tid >> 1;
    const int gcb  = (tid & 1) * 16;
    const float* Ag = Abase + (size_t)(m0 + grow) * KD + gcb;
    const float* Wg = W     + (size_t)(n0 + grow) * KD + gcb;
    const uint32_t sArow = (uint32_t)(grow * GPAD + gcb) * 4u;
    const uint32_t sWrow = sArow + 128u * GPAD * 4u;

    // fragment smem offsets (floats)
    int aoff[4], boff[4];
#pragma unroll
    for (int mf = 0; mf < 4; mf++) aoff[mf] = (wm * 64 + mf * 16 + lq) * GPAD + lr;
#pragma unroll
    for (int nf = 0; nf < 4; nf++) boff[nf] = 128 * GPAD + (wn * 32 + nf * 8 + lq) * GPAD + lr;

    float acc[4][4][4];
#pragma unroll
    for (int i = 0; i < 4; i++)
#pragma unroll
        for (int j = 0; j < 4; j++)
#pragma unroll
            for (int e = 0; e < 4; e++) acc[i][j][e] = 0.f;

    // prologue: stage 0
    {
        uint32_t sb = smb;
#pragma unroll
        for (int j = 0; j < 4; j++) {
            cpa16(sb + sArow + j * 16, Ag + j * 4);
            cpa16(sb + sWrow + j * 16, Wg + j * 4);
        }
        asm volatile("cp.async.commit_group;" ::: "memory");
    }

    for (int t = 0; t < NKT; t++) {
        if (t + 1 < NKT) {
            uint32_t sb = smb + ((t + 1) & 1) * (uint32_t)(STAGE_FLOATS * 4);
            const float* ag = Ag + (t + 1) * 32;
            const float* wg = Wg + (t + 1) * 32;
#pragma unroll
            for (int j = 0; j < 4; j++) {
                cpa16(sb + sArow + j * 16, ag + j * 4);
                cpa16(sb + sWrow + j * 16, wg + j * 4);
            }
            asm volatile("cp.async.commit_group;" ::: "memory");
            asm volatile("cp.async.wait_group 1;" ::: "memory");
        } else {
            asm volatile("cp.async.wait_group 0;" ::: "memory");
        }
        __syncthreads();

        const float* st = sm + (t & 1) * STAGE_FLOATS;
#pragma unroll
        for (int k0 = 0; k0 < 32; k0 += 8) {
            uint32_t af[4][4], bf[4][2];
#pragma unroll
            for (int mf = 0; mf < 4; mf++) {
                af[mf][0] = f2tf32(st[aoff[mf] + k0]);
                af[mf][1] = f2tf32(st[aoff[mf] + 8 * GPAD + k0]);
                af[mf][2] = f2tf32(st[aoff[mf] + k0 + 4]);
                af[mf][3] = f2tf32(st[aoff[mf] + 8 * GPAD + k0 + 4]);
            }
#pragma unroll
            for (int nf = 0; nf < 4; nf++) {
                bf[nf][0] = f2tf32(st[boff[nf] + k0]);
                bf[nf][1] = f2tf32(st[boff[nf] + k0 + 4]);
            }
#pragma unroll
            for (int mf = 0; mf < 4; mf++)
#pragma unroll
                for (int nf = 0; nf < 4; nf++)
                    mma_tf32(acc[mf][nf], af[mf], bf[nf]);
        }
        __syncthreads();
    }

    // epilogue: acc fragment layout:
    // c0: (row = base+lq,    col = f0)   c1: (row,  col f0+1)
    // c2: (row = base+lq+8,  col = f0)   c3: (row+8, col f0+1)
#pragma unroll
    for (int mf = 0; mf < 4; mf++) {
#pragma unroll
        for (int nf = 0; nf < 4; nf++) {
            const int f0 = n0 + wn * 32 + nf * 8 + lr * 2;
            const int r0 = m0 + wm * 64 + mf * 16 + lq;
            const float b0 = bias[f0], b1 = bias[f0 + 1];
            float2 v0 = make_float2(acc[mf][nf][0] + b0, acc[mf][nf][1] + b1);
            float2 v1 = make_float2(acc[mf][nf][2] + b0, acc[mf][nf][3] + b1);
            if (MODE == 0) {
                const int which = f0 >> 10;
                const int fc = f0 & 1023;
                const int hh = fc >> 6;
                const int dd = fc & 63;
                float* dst = (which == 0) ? g_q : (which == 1) ? g_k : g_v;
                const int bb0 = r0 >> 11, tt0 = r0 & 2047;
                const int r1 = r0 + 8;
                const int bb1 = r1 >> 11, tt1 = r1 & 2047;
                *(float2*)(dst + (((size_t)(bb0 * Hn + hh) * Tn + tt0) * Dn + dd)) = v0;
                *(float2*)(dst + (((size_t)(bb1 * Hn + hh) * Tn + tt1) * Dn + dd)) = v1;
            } else {
                *(float2*)(out + (size_t)r0 * Cn + f0)       = v0;
                *(float2*)(out + (size_t)(r0 + 8) * Cn + f0) = v1;
            }
        }
    }
}

// ---------------------------------------------------------------------------
// Flash attention with additive bias (SIMT fp32). Br=Bc=128, D=64, 256 threads.
// grid: (T/128, H, B)
// ---------------------------------------------------------------------------
#define ATTN_SMEM_FLOATS (64*132 + 64*132 + 128*64 + 128*132 + 3*128)
#define ATTN_SMEM_BYTES  (ATTN_SMEM_FLOATS * 4)

__global__ __launch_bounds__(256, 1)
void attn_kernel(const float* __restrict__ bias)
{
    extern __shared__ float smf[];
    float* Qt  = smf;
    float* Kt  = Qt + 64 * 132;
    float* Vs  = Kt + 64 * 132;
    float* Ps  = Vs + 128 * 64;
    float* m_s = Ps + 128 * 132;
    float* l_s = m_s + 128;
    float* al_s = l_s + 128;

    const int tid = threadIdx.x;
    const int tx = tid & 15;
    const int ty = tid >> 4;
    const int qt = blockIdx.x;
    const int h  = blockIdx.y;
    const int b  = blockIdx.z;

    const size_t headoff = ((size_t)(b * Hn + h)) * Tn * Dn;
    const float* qg = g_q + headoff + (size_t)qt * 128 * Dn;
    const float* kg = g_k + headoff;
    const float* vg = g_v + headoff;

    {
        int r  = tid & 127;
        int dv = tid >> 7;
#pragma unroll
        for (int p = 0; p < 8; p++) {
            int d0 = (p * 2 + dv) * 4;
            float4 q4 = *(const float4*)(qg + r * 64 + d0);
            Qt[(d0 + 0) * 132 + r] = q4.x * 0.125f;
            Qt[(d0 + 1) * 132 + r] = q4.y * 0.125f;
            Qt[(d0 + 2) * 132 + r] = q4.z * 0.125f;
            Qt[(d0 + 3) * 132 + r] = q4.w * 0.125f;
        }
    }
    if (tid < 128) { m_s[tid] = -INFINITY; l_s[tid] = 0.f; }

    float o[8][4];
#pragma unroll
    for (int i = 0; i < 8; i++)
#pragma unroll
        for (int j = 0; j < 4; j++) o[i][j] = 0.f;

    for (int kt = 0; kt < 16; kt++) {
        __syncthreads();
        {
            int r  = tid & 127;
            int dv = tid >> 7;
            const float* kp = kg + (size_t)(kt * 128 + r) * 64;
#pragma unroll
            for (int p = 0; p < 8; p++) {
                int d0 = (p * 2 + dv) * 4;
                float4 k4 = *(const float4*)(kp + d0);
                Kt[(d0 + 0) * 132 + r] = k4.x;
                Kt[(d0 + 1) * 132 + r] = k4.y;
                Kt[(d0 + 2) * 132 + r] = k4.z;
                Kt[(d0 + 3) * 132 + r] = k4.w;
            }
        }
        {
            int rr = tid >> 4;
            int dd = (tid & 15) * 4;
            const float* vp = vg + (size_t)kt * 128 * 64;
#pragma unroll
            for (int p = 0; p < 8; p++) {
                int row = p * 16 + rr;
                *(float4*)&Vs[row * 64 + dd] = *(const float4*)(vp + row * 64 + dd);
            }
        }
        __syncthreads();

        float s[8][8];
#pragma unroll
        for (int i = 0; i < 8; i++)
#pragma unroll
            for (int j = 0; j < 8; j++) s[i][j] = 0.f;

        for (int d = 0; d < 64; d++) {
            float4 a0 = *(const float4*)&Qt[d * 132 + ty * 8];
            float4 a1 = *(const float4*)&Qt[d * 132 + ty * 8 + 4];
            float4 b0 = *(const float4*)&Kt[d * 132 + tx * 8];
            float4 b1 = *(const float4*)&Kt[d * 132 + tx * 8 + 4];
            float a[8] = {a0.x, a0.y, a0.z, a0.w, a1.x, a1.y, a1.z, a1.w};
            float w[8] = {b0.x, b0.y, b0.z, b0.w, b1.x, b1.y, b1.z, b1.w};
#pragma unroll
            for (int i = 0; i < 8; i++)
#pragma unroll
                for (int j = 0; j < 8; j++)
                    s[i][j] += a[i] * w[j];
        }

        const float* bp = bias + ((size_t)b * Tn + qt * 128) * Tn + (size_t)kt * 128;
#pragma unroll
        for (int i = 0; i < 8; i++) {
            int rr = ty * 8 + i;
            float4 b40 = *(const float4*)(bp + (size_t)rr * Tn + tx * 8);
            float4 b41 = *(const float4*)(bp + (size_t)rr * Tn + tx * 8 + 4);
            float4 p0 = make_float4(s[i][0] + b40.x, s[i][1] + b40.y,
                                    s[i][2] + b40.z, s[i][3] + b40.w);
            float4 p1 = make_float4(s[i][4] + b41.x, s[i][5] + b41.y,
                                    s[i][6] + b41.z, s[i][7] + b41.w);
            *(float4*)&Ps[rr * 132 + tx * 8]     = p0;
            *(float4*)&Ps[rr * 132 + tx * 8 + 4] = p1;
        }
        __syncthreads();

        if (tid < 128) {
            float mold = m_s[tid];
            float mnew = mold;
            const float* pr = Ps + tid * 132;
#pragma unroll 16
            for (int c = 0; c < 128; c++) mnew = fmaxf(mnew, pr[c]);
            float alpha = __expf(mold - mnew);
            m_s[tid]  = mnew;
            al_s[tid] = alpha;
            l_s[tid] *= alpha;
        }
        __syncthreads();

#pragma unroll
        for (int i = 0; i < 8; i++) {
            float a = al_s[ty * 8 + i];
#pragma unroll
            for (int j = 0; j < 4; j++) o[i][j] *= a;
        }

        {
            int rr = tid >> 1;
            int cb = (tid & 1) * 64;
            float mr = m_s[rr];
            float* pr = Ps + rr * 132 + cb;
            float psum = 0.f;
#pragma unroll 16
            for (int k = 0; k < 64; k++) {
                float p = __expf(pr[k] - mr);
                pr[k] = p;
                psum += p;
            }
            psum += __shfl_xor_sync(0xffffffffu, psum, 1);
            if ((tid & 1) == 0) l_s[rr] += psum;
        }
        __syncthreads();

        for (int c = 0; c < 128; c++) {
            float4 v4 = *(const float4*)&Vs[c * 64 + tx * 4];
#pragma unroll
            for (int i = 0; i < 8; i++) {
                float p = Ps[(ty * 8 + i) * 132 + c];
                o[i][0] += p * v4.x;
                o[i][1] += p * v4.y;
                o[i][2] += p * v4.z;
                o[i][3] += p * v4.w;
            }
        }
    }

    float* og = g_o + ((size_t)b * Tn + (size_t)qt * 128) * Cn + h * Dn;
#pragma unroll
    for (int i = 0; i < 8; i++) {
        int rr = ty * 8 + i;
        float inv = 1.0f / l_s[rr];
        float4 o4 = make_float4(o[i][0] * inv, o[i][1] * inv,
                                o[i][2] * inv, o[i][3] * inv);
        *(float4*)(og + (size_t)rr * Cn + tx * 4) = o4;
    }
}

// ---------------------------------------------------------------------------
extern "C" void kernel_launch(void* const* d_in, const int* in_sizes, int n_in,
                              void* d_out, int out_size)
{
    const float* x         = (const float*)d_in[0];
    const float* attn_bias = (const float*)d_in[1];
    const float* qkv_w     = (const float*)d_in[2];
    const float* qkv_b     = (const float*)d_in[3];
    const float* out_w     = (const float*)d_in[4];
    const float* out_b     = (const float*)d_in[5];
    float* out = (float*)d_out;
    (void)in_sizes; (void)n_in; (void)out_size;

    cudaFuncSetAttribute(gemm_mma<0>, cudaFuncAttributeMaxDynamicSharedMemorySize,
                         GEMM_SMEM_BYTES);
    cudaFuncSetAttribute(gemm_mma<1>, cudaFuncAttributeMaxDynamicSharedMemorySize,
                         GEMM_SMEM_BYTES);
    cudaFuncSetAttribute(attn_kernel, cudaFuncAttributeMaxDynamicSharedMemorySize,
                         ATTN_SMEM_BYTES);

    // QKV projection (tf32 mma.sync): [8192,1024] @ [3072,1024]^T -> q/k/v scatter
    gemm_mma<0><<<dim3(3072 / 128, 8192 / 128), 256, GEMM_SMEM_BYTES>>>(x, qkv_w, qkv_b, nullptr);

    // Attention (flash, online softmax, additive bias)
    attn_kernel<<<dim3(Tn / 128, Hn, Bsz), 256, ATTN_SMEM_BYTES>>>(attn_bias);

    // Output projection (tf32 mma.sync): [8192,1024] @ [1024,1024]^T
    gemm_mma<1><<<dim3(1024 / 128, 8192 / 128), 256, GEMM_SMEM_BYTES>>>(nullptr, out_w, out_b, out);
}

// round 4
// speedup vs baseline: 1.5288x; 1.1249x over previous
#include <cuda_runtime.h>
#include <math.h>
#include <stdint.h>

#define Bsz 4
#define Tn  2048
#define Cn  1024
#define Hn  16
#define Dn  64

// Scratch (static device globals — no allocation allowed)
__device__ float g_q[(size_t)Bsz * Hn * Tn * Dn];   // [B,H,T,D]
__device__ float g_k[(size_t)Bsz * Hn * Tn * Dn];
__device__ float g_v[(size_t)Bsz * Hn * Tn * Dn];
__device__ float g_o[(size_t)Bsz * Tn * Cn];        // [B,T,C]

// ---------------------------------------------------------------------------
// helpers
// ---------------------------------------------------------------------------
__device__ __forceinline__ uint32_t smem_u32(const void* p) {
    uint32_t a;
    asm("{ .reg .u64 t; cvta.to.shared.u64 t, %1; cvt.u32.u64 %0, t; }"
        : "=r"(a) : "l"(p));
    return a;
}

__device__ __forceinline__ void cpa16(uint32_t s, const void* g) {
    asm volatile("cp.async.cg.shared.global [%0], [%1], 16;"
                 :: "r"(s), "l"(g) : "memory");
}

__device__ __forceinline__ uint32_t f2tf32(float f) {
    uint32_t r;
    asm("cvt.rna.tf32.f32 %0, %1;" : "=r"(r) : "f"(f));
    return r;
}

__device__ __forceinline__ float ex2a(float x) {
    float y;
    asm("ex2.approx.f32 %0, %1;" : "=f"(y) : "f"(x));
    return y;
}

// D += A(16x8) * B(8x8)^T, tf32, fp32 accum
__device__ __forceinline__ void mma_tf32(float* d, const uint32_t* a, const uint32_t* b) {
    asm volatile(
        "mma.sync.aligned.m16n8k8.row.col.f32.tf32.tf32.f32 "
        "{%0,%1,%2,%3}, {%4,%5,%6,%7}, {%8,%9}, {%0,%1,%2,%3};"
        : "+f"(d[0]), "+f"(d[1]), "+f"(d[2]), "+f"(d[3])
        : "r"(a[0]), "r"(a[1]), "r"(a[2]), "r"(a[3]), "r"(b[0]), "r"(b[1]));
}

// ---------------------------------------------------------------------------
// tf32 mma.sync GEMM: out[m][n] = sum_k A[m][k] * W[n][k] + bias[n]
// BM=BN=128, BK=32, K=1024, 256 threads (8 warps in 2x4), warp tile 64x32.
// MODE 0: A = x, scatter into g_q/g_k/g_v.  MODE 1: A = g_o, row-major out.
// ---------------------------------------------------------------------------
#define GPAD 36
#define STAGE_FLOATS (2 * 128 * GPAD)
#define GEMM_SMEM_BYTES (2 * STAGE_FLOATS * 4)

template <int MODE>
__global__ __launch_bounds__(256, 1)
void gemm_mma(const float* __restrict__ A, const float* __restrict__ W,
              const float* __restrict__ bias, float* __restrict__ out)
{
    constexpr int KD  = 1024;
    constexpr int NKT = KD / 32;

    extern __shared__ float sm[];
    const uint32_t smb = smem_u32(sm);

    const int tid  = threadIdx.x;
    const int wid  = tid >> 5;
    const int lane = tid & 31;
    const int wm   = wid >> 2;
    const int wn   = wid & 3;
    const int lq   = lane >> 2;
    const int lr   = lane & 3;
    const int n0 = blockIdx.x * 128;
    const int m0 = blockIdx.y * 128;

    const float* Abase = (MODE == 1) ? g_o : A;

    const int grow = tid >> 1;
    const int gcb  = (tid & 1) * 16;
    const float* Ag = Abase + (size_t)(m0 + grow) * KD + gcb;
    const float* Wg = W     + (size_t)(n0 + grow) * KD + gcb;
    const uint32_t sArow = (uint32_t)(grow * GPAD + gcb) * 4u;
    const uint32_t sWrow = sArow + 128u * GPAD * 4u;

    int aoff[4], boff[4];
#pragma unroll
    for (int mf = 0; mf < 4; mf++) aoff[mf] = (wm * 64 + mf * 16 + lq) * GPAD + lr;
#pragma unroll
    for (int nf = 0; nf < 4; nf++) boff[nf] = 128 * GPAD + (wn * 32 + nf * 8 + lq) * GPAD + lr;

    float acc[4][4][4];
#pragma unroll
    for (int i = 0; i < 4; i++)
#pragma unroll
        for (int j = 0; j < 4; j++)
#pragma unroll
            for (int e = 0; e < 4; e++) acc[i][j][e] = 0.f;

    {
        uint32_t sb = smb;
#pragma unroll
        for (int j = 0; j < 4; j++) {
            cpa16(sb + sArow + j * 16, Ag + j * 4);
            cpa16(sb + sWrow + j * 16, Wg + j * 4);
        }
        asm volatile("cp.async.commit_group;" ::: "memory");
    }

    for (int t = 0; t < NKT; t++) {
        if (t + 1 < NKT) {
            uint32_t sb = smb + ((t + 1) & 1) * (uint32_t)(STAGE_FLOATS * 4);
            const float* ag = Ag + (t + 1) * 32;
            const float* wg = Wg + (t + 1) * 32;
#pragma unroll
            for (int j = 0; j < 4; j++) {
                cpa16(sb + sArow + j * 16, ag + j * 4);
                cpa16(sb + sWrow + j * 16, wg + j * 4);
            }
            asm volatile("cp.async.commit_group;" ::: "memory");
            asm volatile("cp.async.wait_group 1;" ::: "memory");
        } else {
            asm volatile("cp.async.wait_group 0;" ::: "memory");
        }
        __syncthreads();

        const float* st = sm + (t & 1) * STAGE_FLOATS;
#pragma unroll
        for (int k0 = 0; k0 < 32; k0 += 8) {
            uint32_t af[4][4], bf[4][2];
#pragma unroll
            for (int mf = 0; mf < 4; mf++) {
                af[mf][0] = f2tf32(st[aoff[mf] + k0]);
                af[mf][1] = f2tf32(st[aoff[mf] + 8 * GPAD + k0]);
                af[mf][2] = f2tf32(st[aoff[mf] + k0 + 4]);
                af[mf][3] = f2tf32(st[aoff[mf] + 8 * GPAD + k0 + 4]);
            }
#pragma unroll
            for (int nf = 0; nf < 4; nf++) {
                bf[nf][0] = f2tf32(st[boff[nf] + k0]);
                bf[nf][1] = f2tf32(st[boff[nf] + k0 + 4]);
            }
#pragma unroll
            for (int mf = 0; mf < 4; mf++)
#pragma unroll
                for (int nf = 0; nf < 4; nf++)
                    mma_tf32(acc[mf][nf], af[mf], bf[nf]);
        }
        __syncthreads();
    }

#pragma unroll
    for (int mf = 0; mf < 4; mf++) {
#pragma unroll
        for (int nf = 0; nf < 4; nf++) {
            const int f0 = n0 + wn * 32 + nf * 8 + lr * 2;
            const int r0 = m0 + wm * 64 + mf * 16 + lq;
            const float b0 = bias[f0], b1 = bias[f0 + 1];
            float2 v0 = make_float2(acc[mf][nf][0] + b0, acc[mf][nf][1] + b1);
            float2 v1 = make_float2(acc[mf][nf][2] + b0, acc[mf][nf][3] + b1);
            if (MODE == 0) {
                const int which = f0 >> 10;
                const int fc = f0 & 1023;
                const int hh = fc >> 6;
                const int dd = fc & 63;
                float* dst = (which == 0) ? g_q : (which == 1) ? g_k : g_v;
                const int bb0 = r0 >> 11, tt0 = r0 & 2047;
                const int r1 = r0 + 8;
                const int bb1 = r1 >> 11, tt1 = r1 & 2047;
                *(float2*)(dst + (((size_t)(bb0 * Hn + hh) * Tn + tt0) * Dn + dd)) = v0;
                *(float2*)(dst + (((size_t)(bb1 * Hn + hh) * Tn + tt1) * Dn + dd)) = v1;
            } else {
                *(float2*)(out + (size_t)r0 * Cn + f0)       = v0;
                *(float2*)(out + (size_t)(r0 + 8) * Cn + f0) = v1;
            }
        }
    }
}

// ---------------------------------------------------------------------------
// Flash attention, tf32 mma.sync. Br=128, Bc=128, D=64, 256 threads (8 warps).
// Warp w owns q-rows w*16..w*16+15 across full N -> softmax stays in-warp.
// Base-2 logits (q pre-scaled by 0.125*log2e, bias fma'd with log2e), ex2.approx.
// grid: (T/128, H, B)
// ---------------------------------------------------------------------------
#define AKP 68                      // K tile pad (floats)
#define AVP 72                      // V tile pad
#define APP 132                     // P pane pad
#define A_KSTG (128 * AKP)
#define A_VSTG (128 * AVP)
#define ATTN_SMEM_FLOATS (2 * A_KSTG + 2 * A_VSTG + 128 * APP)
#define ATTN_SMEM_BYTES  (ATTN_SMEM_FLOATS * 4)

__global__ __launch_bounds__(256, 1)
void attn_mma(const float* __restrict__ bias)
{
    extern __shared__ float sm[];
    float* Ks = sm;                          // 2 x 128 x AKP
    float* Vs = sm + 2 * A_KSTG;             // 2 x 128 x AVP
    float* Ps = Vs + 2 * A_VSTG;             // 128 x APP
    const uint32_t smbK = smem_u32(Ks);
    const uint32_t smbV = smem_u32(Vs);

    const int tid  = threadIdx.x;
    const int wid  = tid >> 5;
    const int lane = tid & 31;
    const int lq   = lane >> 2;
    const int lr   = lane & 3;
    const int qt = blockIdx.x;
    const int h  = blockIdx.y;
    const int b  = blockIdx.z;

    const size_t headoff = ((size_t)(b * Hn + h)) * Tn * Dn;
    const float* qg = g_q + headoff + (size_t)qt * 128 * Dn;
    const float* kg = g_k + headoff;
    const float* vg = g_v + headoff;

    const int r_lo = wid * 16 + lq;          // local q row (lo half)
    constexpr float L2E = 1.44269504f;

    // Q fragments, resident in registers, scaled by 1/8 * log2(e)
    uint32_t qf[8][4];
    {
        const float qs = 0.125f * L2E;
#pragma unroll
        for (int ks = 0; ks < 8; ks++) {
            qf[ks][0] = f2tf32(qg[(size_t)r_lo * 64 + ks * 8 + lr] * qs);
            qf[ks][1] = f2tf32(qg[(size_t)(r_lo + 8) * 64 + ks * 8 + lr] * qs);
            qf[ks][2] = f2tf32(qg[(size_t)r_lo * 64 + ks * 8 + lr + 4] * qs);
            qf[ks][3] = f2tf32(qg[(size_t)(r_lo + 8) * 64 + ks * 8 + lr + 4] * qs);
        }
    }

    float m_lo = -1e30f, m_hi = -1e30f, l_lo = 0.f, l_hi = 0.f;
    float acc_o[8][4];
#pragma unroll
    for (int i = 0; i < 8; i++)
#pragma unroll
        for (int e = 0; e < 4; e++) acc_o[i][e] = 0.f;

    // tile loader: 8 float4 each for K and V per thread, coalesced
#define LOAD_KV(KT, STG) do {                                                   \
        const float* kp = kg + (size_t)(KT) * 128 * 64;                         \
        const float* vp = vg + (size_t)(KT) * 128 * 64;                         \
        uint32_t kdst = smbK + (uint32_t)(STG) * (A_KSTG * 4);                  \
        uint32_t vdst = smbV + (uint32_t)(STG) * (A_VSTG * 4);                  \
        _Pragma("unroll")                                                       \
        for (int j = 0; j < 8; j++) {                                           \
            int idx = j * 256 + tid;                                            \
            int row = idx >> 4, c4 = (idx & 15) * 4;                            \
            cpa16(kdst + (uint32_t)(row * AKP + c4) * 4u, kp + row * 64 + c4);  \
            cpa16(vdst + (uint32_t)(row * AVP + c4) * 4u, vp + row * 64 + c4);  \
        }                                                                       \
        asm volatile("cp.async.commit_group;" ::: "memory");                    \
    } while (0)

    LOAD_KV(0, 0);

    const float* bias_lo = bias + ((size_t)b * Tn + qt * 128 + r_lo) * Tn;
    const float* bias_hi = bias_lo + 8 * Tn;

    for (int kt = 0; kt < 16; kt++) {
        if (kt + 1 < 16) {
            LOAD_KV(kt + 1, (kt + 1) & 1);
            asm volatile("cp.async.wait_group 1;" ::: "memory");
        } else {
            asm volatile("cp.async.wait_group 0;" ::: "memory");
        }
        __syncthreads();

        const float* K0 = Ks + (kt & 1) * A_KSTG;
        const float* V0 = Vs + (kt & 1) * A_VSTG;

        // ---- S = Q @ K^T (base-2 logits, bias pending) ----
        float acc_s[16][4];
#pragma unroll
        for (int nf = 0; nf < 16; nf++)
#pragma unroll
            for (int e = 0; e < 4; e++) acc_s[nf][e] = 0.f;

#pragma unroll
        for (int nf = 0; nf < 16; nf++) {
            const float* kr = K0 + (nf * 8 + lq) * AKP;
#pragma unroll
            for (int ks = 0; ks < 8; ks++) {
                uint32_t bf[2] = { f2tf32(kr[ks * 8 + lr]),
                                   f2tf32(kr[ks * 8 + lr + 4]) };
                mma_tf32(acc_s[nf], qf[ks], bf);
            }
        }

        // ---- bias add (x L2E) + row max ----
        float nm_lo = m_lo, nm_hi = m_hi;
#pragma unroll
        for (int nf = 0; nf < 16; nf++) {
            const int c = kt * 128 + nf * 8 + lr * 2;
            float2 b0 = *(const float2*)(bias_lo + c);
            float2 b1 = *(const float2*)(bias_hi + c);
            acc_s[nf][0] = fmaf(b0.x, L2E, acc_s[nf][0]);
            acc_s[nf][1] = fmaf(b0.y, L2E, acc_s[nf][1]);
            acc_s[nf][2] = fmaf(b1.x, L2E, acc_s[nf][2]);
            acc_s[nf][3] = fmaf(b1.y, L2E, acc_s[nf][3]);
            nm_lo = fmaxf(nm_lo, fmaxf(acc_s[nf][0], acc_s[nf][1]));
            nm_hi = fmaxf(nm_hi, fmaxf(acc_s[nf][2], acc_s[nf][3]));
        }
        nm_lo = fmaxf(nm_lo, __shfl_xor_sync(0xffffffffu, nm_lo, 1));
        nm_lo = fmaxf(nm_lo, __shfl_xor_sync(0xffffffffu, nm_lo, 2));
        nm_hi = fmaxf(nm_hi, __shfl_xor_sync(0xffffffffu, nm_hi, 1));
        nm_hi = fmaxf(nm_hi, __shfl_xor_sync(0xffffffffu, nm_hi, 2));

        const float alpha_lo = ex2a(m_lo - nm_lo);
        const float alpha_hi = ex2a(m_hi - nm_hi);
        m_lo = nm_lo; m_hi = nm_hi;

        // ---- exponentiate, partial row sums, stash P in warp-private pane ----
        float s_lo = 0.f, s_hi = 0.f;
        float* p_lo = Ps + (size_t)(wid * 16 + lq) * APP;
        float* p_hi = p_lo + 8 * APP;
#pragma unroll
        for (int nf = 0; nf < 16; nf++) {
            float p0 = ex2a(acc_s[nf][0] - m_lo);
            float p1 = ex2a(acc_s[nf][1] - m_lo);
            float p2 = ex2a(acc_s[nf][2] - m_hi);
            float p3 = ex2a(acc_s[nf][3] - m_hi);
            s_lo += p0 + p1;
            s_hi += p2 + p3;
            *(float2*)(p_lo + nf * 8 + lr * 2) = make_float2(p0, p1);
            *(float2*)(p_hi + nf * 8 + lr * 2) = make_float2(p2, p3);
        }
        s_lo += __shfl_xor_sync(0xffffffffu, s_lo, 1);
        s_lo += __shfl_xor_sync(0xffffffffu, s_lo, 2);
        s_hi += __shfl_xor_sync(0xffffffffu, s_hi, 1);
        s_hi += __shfl_xor_sync(0xffffffffu, s_hi, 2);
        l_lo = l_lo * alpha_lo + s_lo;
        l_hi = l_hi * alpha_hi + s_hi;

#pragma unroll
        for (int nf = 0; nf < 8; nf++) {
            acc_o[nf][0] *= alpha_lo;
            acc_o[nf][1] *= alpha_lo;
            acc_o[nf][2] *= alpha_hi;
            acc_o[nf][3] *= alpha_hi;
        }
        __syncwarp();

        // ---- O += P @ V ----
        const float* pw = Ps + (size_t)(wid * 16) * APP;
#pragma unroll
        for (int kk = 0; kk < 16; kk++) {
            uint32_t pf[4] = {
                f2tf32(pw[(size_t)lq * APP + kk * 8 + lr]),
                f2tf32(pw[(size_t)(lq + 8) * APP + kk * 8 + lr]),
                f2tf32(pw[(size_t)lq * APP + kk * 8 + lr + 4]),
                f2tf32(pw[(size_t)(lq + 8) * APP + kk * 8 + lr + 4])
            };
#pragma unroll
            for (int nf = 0; nf < 8; nf++) {
                uint32_t vf[2] = {
                    f2tf32(V0[(kk * 8 + lr) * AVP + nf * 8 + lq]),
                    f2tf32(V0[(kk * 8 + lr + 4) * AVP + nf * 8 + lq])
                };
                mma_tf32(acc_o[nf], pf, vf);
            }
        }
        __syncthreads();
    }

    // ---- normalize + write to g_o [B,T,C] ----
    const float inv_lo = 1.f / l_lo;
    const float inv_hi = 1.f / l_hi;
    float* og_lo = g_o + ((size_t)b * Tn + qt * 128 + r_lo) * Cn + h * Dn;
    float* og_hi = og_lo + 8 * Cn;
#pragma unroll
    for (int nf = 0; nf < 8; nf++) {
        *(float2*)(og_lo + nf * 8 + lr * 2) =
            make_float2(acc_o[nf][0] * inv_lo, acc_o[nf][1] * inv_lo);
        *(float2*)(og_hi + nf * 8 + lr * 2) =
            make_float2(acc_o[nf][2] * inv_hi, acc_o[nf][3] * inv_hi);
    }
#undef LOAD_KV
}

// ---------------------------------------------------------------------------
extern "C" void kernel_launch(void* const* d_in, const int* in_sizes, int n_in,
                              void* d_out, int out_size)
{
    const float* x         = (const float*)d_in[0];
    const float* attn_bias = (const float*)d_in[1];
    const float* qkv_w     = (const float*)d_in[2];
    const float* qkv_b     = (const float*)d_in[3];
    const float* out_w     = (const float*)d_in[4];
    const float* out_b     = (const float*)d_in[5];
    float* out = (float*)d_out;
    (void)in_sizes; (void)n_in; (void)out_size;

    cudaFuncSetAttribute(gemm_mma<0>, cudaFuncAttributeMaxDynamicSharedMemorySize,
                         GEMM_SMEM_BYTES);
    cudaFuncSetAttribute(gemm_mma<1>, cudaFuncAttributeMaxDynamicSharedMemorySize,
                         GEMM_SMEM_BYTES);
    cudaFuncSetAttribute(attn_mma, cudaFuncAttributeMaxDynamicSharedMemorySize,
                         ATTN_SMEM_BYTES);

    // QKV projection (tf32 mma.sync): [8192,1024] @ [3072,1024]^T -> q/k/v scatter
    gemm_mma<0><<<dim3(3072 / 128, 8192 / 128), 256, GEMM_SMEM_BYTES>>>(x, qkv_w, qkv_b, nullptr);

    // Attention (flash, tf32 mma.sync, base-2 online softmax)
    attn_mma<<<dim3(Tn / 128, Hn, Bsz), 256, ATTN_SMEM_BYTES>>>(attn_bias);

    // Output projection (tf32 mma.sync): [8192,1024] @ [1024,1024]^T
    gemm_mma<1><<<dim3(1024 / 128, 8192 / 128), 256, GEMM_SMEM_BYTES>>>(nullptr, out_w, out_b, out);
}

// round 5
// speedup vs baseline: 2.6028x; 1.7025x over previous
#include <cuda_runtime.h>
#include <math.h>
#include <stdint.h>

#define Bsz 4
#define Tn  2048
#define Cn  1024
#define Hn  16
#define Dn  64

// Scratch (static device globals — no allocation allowed)
__device__ float g_q[(size_t)Bsz * Hn * Tn * Dn];   // [B,H,T,D] (tf32-rounded)
__device__ float g_k[(size_t)Bsz * Hn * Tn * Dn];
__device__ float g_v[(size_t)Bsz * Hn * Tn * Dn];
__device__ float g_o[(size_t)Bsz * Tn * Cn];        // [B,T,C]  (tf32-rounded)

// ---------------------------------------------------------------------------
// helpers
// ---------------------------------------------------------------------------
__device__ __forceinline__ uint32_t smem_u32(const void* p) {
    uint32_t a;
    asm("{ .reg .u64 t; cvta.to.shared.u64 t, %1; cvt.u32.u64 %0, t; }"
        : "=r"(a) : "l"(p));
    return a;
}

__device__ __forceinline__ void cpa16(uint32_t s, const void* g) {
    asm volatile("cp.async.cg.shared.global [%0], [%1], 16;"
                 :: "r"(s), "l"(g) : "memory");
}

__device__ __forceinline__ uint32_t f2tf32(float f) {   // rna round (off hot path only)
    uint32_t r;
    asm("cvt.rna.tf32.f32 %0, %1;" : "=r"(r) : "f"(f));
    return r;
}

__device__ __forceinline__ float ex2a(float x) {
    float y;
    asm("ex2.approx.f32 %0, %1;" : "=f"(y) : "f"(x));
    return y;
}

// D += A(16x8) * B(8x8)^T, tf32 (raw fp32 bits: HW uses top 19 bits), fp32 accum
__device__ __forceinline__ void mma_tf32(float* d, const uint32_t* a, const uint32_t* b) {
    asm volatile(
        "mma.sync.aligned.m16n8k8.row.col.f32.tf32.tf32.f32 "
        "{%0,%1,%2,%3}, {%4,%5,%6,%7}, {%8,%9}, {%0,%1,%2,%3};"
        : "+f"(d[0]), "+f"(d[1]), "+f"(d[2]), "+f"(d[3])
        : "r"(a[0]), "r"(a[1]), "r"(a[2]), "r"(a[3]), "r"(b[0]), "r"(b[1]));
}

// ---------------------------------------------------------------------------
// tf32 mma.sync GEMM: out[m][n] = sum_k A[m][k] * W[n][k] + bias[n]
// BM=BN=128, BK=32, K=1024, 256 threads (8 warps in 2x4), warp tile 64x32.
// Operands fed as raw fp32 bits (tf32 truncation in HW).
// MODE 0: A = x, scatter tf32-rounded into g_q/g_k/g_v.  MODE 1: row-major out.
// ---------------------------------------------------------------------------
#define GPAD 36
#define STAGE_FLOATS (2 * 128 * GPAD)
#define GEMM_SMEM_BYTES (2 * STAGE_FLOATS * 4)

template <int MODE>
__global__ __launch_bounds__(256, 2)
void gemm_mma(const float* __restrict__ A, const float* __restrict__ W,
              const float* __restrict__ bias, float* __restrict__ out)
{
    constexpr int KD  = 1024;
    constexpr int NKT = KD / 32;

    extern __shared__ float sm[];
    const uint32_t smb = smem_u32(sm);
    const uint32_t* smu = (const uint32_t*)sm;

    const int tid  = threadIdx.x;
    const int wid  = tid >> 5;
    const int lane = tid & 31;
    const int wm   = wid >> 2;
    const int wn   = wid & 3;
    const int lq   = lane >> 2;
    const int lr   = lane & 3;
    const int n0 = blockIdx.x * 128;
    const int m0 = blockIdx.y * 128;

    const float* Abase = (MODE == 1) ? g_o : A;

    const int grow = tid >> 1;
    const int gcb  = (tid & 1) * 16;
    const float* Ag = Abase + (size_t)(m0 + grow) * KD + gcb;
    const float* Wg = W     + (size_t)(n0 + grow) * KD + gcb;
    const uint32_t sArow = (uint32_t)(grow * GPAD + gcb) * 4u;
    const uint32_t sWrow = sArow + 128u * GPAD * 4u;

    int aoff[4], boff[4];
#pragma unroll
    for (int mf = 0; mf < 4; mf++) aoff[mf] = (wm * 64 + mf * 16 + lq) * GPAD + lr;
#pragma unroll
    for (int nf = 0; nf < 4; nf++) boff[nf] = 128 * GPAD + (wn * 32 + nf * 8 + lq) * GPAD + lr;

    float acc[4][4][4];
#pragma unroll
    for (int i = 0; i < 4; i++)
#pragma unroll
        for (int j = 0; j < 4; j++)
#pragma unroll
            for (int e = 0; e < 4; e++) acc[i][j][e] = 0.f;

    {
        uint32_t sb = smb;
#pragma unroll
        for (int j = 0; j < 4; j++) {
            cpa16(sb + sArow + j * 16, Ag + j * 4);
            cpa16(sb + sWrow + j * 16, Wg + j * 4);
        }
        asm volatile("cp.async.commit_group;" ::: "memory");
    }

    for (int t = 0; t < NKT; t++) {
        if (t + 1 < NKT) {
            uint32_t sb = smb + ((t + 1) & 1) * (uint32_t)(STAGE_FLOATS * 4);
            const float* ag = Ag + (t + 1) * 32;
            const float* wg = Wg + (t + 1) * 32;
#pragma unroll
            for (int j = 0; j < 4; j++) {
                cpa16(sb + sArow + j * 16, ag + j * 4);
                cpa16(sb + sWrow + j * 16, wg + j * 4);
            }
            asm volatile("cp.async.commit_group;" ::: "memory");
            asm volatile("cp.async.wait_group 1;" ::: "memory");
        } else {
            asm volatile("cp.async.wait_group 0;" ::: "memory");
        }
        __syncthreads();

        const uint32_t* st = smu + (t & 1) * STAGE_FLOATS;
#pragma unroll
        for (int k0 = 0; k0 < 32; k0 += 8) {
            uint32_t af[4][4], bf[4][2];
#pragma unroll
            for (int mf = 0; mf < 4; mf++) {
                af[mf][0] = st[aoff[mf] + k0];
                af[mf][1] = st[aoff[mf] + 8 * GPAD + k0];
                af[mf][2] = st[aoff[mf] + k0 + 4];
                af[mf][3] = st[aoff[mf] + 8 * GPAD + k0 + 4];
            }
#pragma unroll
            for (int nf = 0; nf < 4; nf++) {
                bf[nf][0] = st[boff[nf] + k0];
                bf[nf][1] = st[boff[nf] + k0 + 4];
            }
#pragma unroll
            for (int mf = 0; mf < 4; mf++)
#pragma unroll
                for (int nf = 0; nf < 4; nf++)
                    mma_tf32(acc[mf][nf], af[mf], bf[nf]);
        }
        __syncthreads();
    }

#pragma unroll
    for (int mf = 0; mf < 4; mf++) {
#pragma unroll
        for (int nf = 0; nf < 4; nf++) {
            const int f0 = n0 + wn * 32 + nf * 8 + lr * 2;
            const int r0 = m0 + wm * 64 + mf * 16 + lq;
            const float b0 = bias[f0], b1 = bias[f0 + 1];
            if (MODE == 0) {
                // pre-round to tf32 (rna) so attention can feed raw bits exactly
                float2 v0 = make_float2(__uint_as_float(f2tf32(acc[mf][nf][0] + b0)),
                                        __uint_as_float(f2tf32(acc[mf][nf][1] + b1)));
                float2 v1 = make_float2(__uint_as_float(f2tf32(acc[mf][nf][2] + b0)),
                                        __uint_as_float(f2tf32(acc[mf][nf][3] + b1)));
                const int which = f0 >> 10;
                const int fc = f0 & 1023;
                const int hh = fc >> 6;
                const int dd = fc & 63;
                float* dst = (which == 0) ? g_q : (which == 1) ? g_k : g_v;
                const int bb0 = r0 >> 11, tt0 = r0 & 2047;
                const int r1 = r0 + 8;
                const int bb1 = r1 >> 11, tt1 = r1 & 2047;
                *(float2*)(dst + (((size_t)(bb0 * Hn + hh) * Tn + tt0) * Dn + dd)) = v0;
                *(float2*)(dst + (((size_t)(bb1 * Hn + hh) * Tn + tt1) * Dn + dd)) = v1;
            } else {
                float2 v0 = make_float2(acc[mf][nf][0] + b0, acc[mf][nf][1] + b1);
                float2 v1 = make_float2(acc[mf][nf][2] + b0, acc[mf][nf][3] + b1);
                *(float2*)(out + (size_t)r0 * Cn + f0)       = v0;
                *(float2*)(out + (size_t)(r0 + 8) * Cn + f0) = v1;
            }
        }
    }
}

// ---------------------------------------------------------------------------
// Flash attention, tf32 mma.sync. Br=128, Bc=128, D=64, 256 threads (8 warps).
// Warp w owns q-rows w*16..w*16+15 across full N -> softmax stays in-warp.
// Inputs g_q/g_k/g_v already tf32-rounded; all fragments fed as raw bits.
// grid: (T/128, H, B)
// ---------------------------------------------------------------------------
#define AKP 68
#define AVP 72
#define APP 132
#define A_KSTG (128 * AKP)
#define A_VSTG (128 * AVP)
#define ATTN_SMEM_FLOATS (2 * A_KSTG + 2 * A_VSTG + 128 * APP)
#define ATTN_SMEM_BYTES  (ATTN_SMEM_FLOATS * 4)

__global__ __launch_bounds__(256, 1)
void attn_mma(const float* __restrict__ bias)
{
    extern __shared__ float sm[];
    float* Ks = sm;
    float* Vs = sm + 2 * A_KSTG;
    float* Ps = Vs + 2 * A_VSTG;
    const uint32_t smbK = smem_u32(Ks);
    const uint32_t smbV = smem_u32(Vs);

    const int tid  = threadIdx.x;
    const int wid  = tid >> 5;
    const int lane = tid & 31;
    const int lq   = lane >> 2;
    const int lr   = lane & 3;
    const int qt = blockIdx.x;
    const int h  = blockIdx.y;
    const int b  = blockIdx.z;

    const size_t headoff = ((size_t)(b * Hn + h)) * Tn * Dn;
    const float* qg = g_q + headoff + (size_t)qt * 128 * Dn;
    const float* kg = g_k + headoff;
    const float* vg = g_v + headoff;

    const int r_lo = wid * 16 + lq;
    constexpr float L2E = 1.44269504f;

    // Q fragments in registers, scaled by 1/8*log2(e), rna-rounded once here
    uint32_t qf[8][4];
    {
        const float qs = 0.125f * L2E;
#pragma unroll
        for (int ks = 0; ks < 8; ks++) {
            qf[ks][0] = f2tf32(qg[(size_t)r_lo * 64 + ks * 8 + lr] * qs);
            qf[ks][1] = f2tf32(qg[(size_t)(r_lo + 8) * 64 + ks * 8 + lr] * qs);
            qf[ks][2] = f2tf32(qg[(size_t)r_lo * 64 + ks * 8 + lr + 4] * qs);
            qf[ks][3] = f2tf32(qg[(size_t)(r_lo + 8) * 64 + ks * 8 + lr + 4] * qs);
        }
    }

    float m_lo = -1e30f, m_hi = -1e30f, l_lo = 0.f, l_hi = 0.f;
    float acc_o[8][4];
#pragma unroll
    for (int i = 0; i < 8; i++)
#pragma unroll
        for (int e = 0; e < 4; e++) acc_o[i][e] = 0.f;

#define LOAD_KV(KT, STG) do {                                                   \
        const float* kp = kg + (size_t)(KT) * 128 * 64;                         \
        const float* vp = vg + (size_t)(KT) * 128 * 64;                         \
        uint32_t kdst = smbK + (uint32_t)(STG) * (A_KSTG * 4);                  \
        uint32_t vdst = smbV + (uint32_t)(STG) * (A_VSTG * 4);                  \
        _Pragma("unroll")                                                       \
        for (int j = 0; j < 8; j++) {                                           \
            int idx = j * 256 + tid;                                            \
            int row = idx >> 4, c4 = (idx & 15) * 4;                            \
            cpa16(kdst + (uint32_t)(row * AKP + c4) * 4u, kp + row * 64 + c4);  \
            cpa16(vdst + (uint32_t)(row * AVP + c4) * 4u, vp + row * 64 + c4);  \
        }                                                                       \
        asm volatile("cp.async.commit_group;" ::: "memory");                    \
    } while (0)

    LOAD_KV(0, 0);

    const float* bias_lo = bias + ((size_t)b * Tn + qt * 128 + r_lo) * Tn;
    const float* bias_hi = bias_lo + 8 * Tn;

    for (int kt = 0; kt < 16; kt++) {
        if (kt + 1 < 16) {
            LOAD_KV(kt + 1, (kt + 1) & 1);
            asm volatile("cp.async.wait_group 1;" ::: "memory");
        } else {
            asm volatile("cp.async.wait_group 0;" ::: "memory");
        }
        __syncthreads();

        const uint32_t* K0 = (const uint32_t*)(Ks + (kt & 1) * A_KSTG);
        const uint32_t* V0 = (const uint32_t*)(Vs + (kt & 1) * A_VSTG);

        // ---- S = Q @ K^T (raw-bit fragments; K pre-rounded) ----
        float acc_s[16][4];
#pragma unroll
        for (int nf = 0; nf < 16; nf++)
#pragma unroll
            for (int e = 0; e < 4; e++) acc_s[nf][e] = 0.f;

#pragma unroll
        for (int nf = 0; nf < 16; nf++) {
            const uint32_t* kr = K0 + (nf * 8 + lq) * AKP;
#pragma unroll
            for (int ks = 0; ks < 8; ks++) {
                uint32_t bf[2] = { kr[ks * 8 + lr], kr[ks * 8 + lr + 4] };
                mma_tf32(acc_s[nf], qf[ks], bf);
            }
        }

        // ---- bias add (x L2E) + row max ----
        float nm_lo = m_lo, nm_hi = m_hi;
#pragma unroll
        for (int nf = 0; nf < 16; nf++) {
            const int c = kt * 128 + nf * 8 + lr * 2;
            float2 b0 = *(const float2*)(bias_lo + c);
            float2 b1 = *(const float2*)(bias_hi + c);
            acc_s[nf][0] = fmaf(b0.x, L2E, acc_s[nf][0]);
            acc_s[nf][1] = fmaf(b0.y, L2E, acc_s[nf][1]);
            acc_s[nf][2] = fmaf(b1.x, L2E, acc_s[nf][2]);
            acc_s[nf][3] = fmaf(b1.y, L2E, acc_s[nf][3]);
            nm_lo = fmaxf(nm_lo, fmaxf(acc_s[nf][0], acc_s[nf][1]));
            nm_hi = fmaxf(nm_hi, fmaxf(acc_s[nf][2], acc_s[nf][3]));
        }
        nm_lo = fmaxf(nm_lo, __shfl_xor_sync(0xffffffffu, nm_lo, 1));
        nm_lo = fmaxf(nm_lo, __shfl_xor_sync(0xffffffffu, nm_lo, 2));
        nm_hi = fmaxf(nm_hi, __shfl_xor_sync(0xffffffffu, nm_hi, 1));
        nm_hi = fmaxf(nm_hi, __shfl_xor_sync(0xffffffffu, nm_hi, 2));

        const float alpha_lo = ex2a(m_lo - nm_lo);
        const float alpha_hi = ex2a(m_hi - nm_hi);
        m_lo = nm_lo; m_hi = nm_hi;

        // ---- exponentiate, partial row sums, stash P in warp-private pane ----
        float s_lo = 0.f, s_hi = 0.f;
        float* p_lo = Ps + (size_t)(wid * 16 + lq) * APP;
        float* p_hi = p_lo + 8 * APP;
#pragma unroll
        for (int nf = 0; nf < 16; nf++) {
            float p0 = ex2a(acc_s[nf][0] - m_lo);
            float p1 = ex2a(acc_s[nf][1] - m_lo);
            float p2 = ex2a(acc_s[nf][2] - m_hi);
            float p3 = ex2a(acc_s[nf][3] - m_hi);
            s_lo += p0 + p1;
            s_hi += p2 + p3;
            *(float2*)(p_lo + nf * 8 + lr * 2) = make_float2(p0, p1);
            *(float2*)(p_hi + nf * 8 + lr * 2) = make_float2(p2, p3);
        }
        s_lo += __shfl_xor_sync(0xffffffffu, s_lo, 1);
        s_lo += __shfl_xor_sync(0xffffffffu, s_lo, 2);
        s_hi += __shfl_xor_sync(0xffffffffu, s_hi, 1);
        s_hi += __shfl_xor_sync(0xffffffffu, s_hi, 2);
        l_lo = l_lo * alpha_lo + s_lo;
        l_hi = l_hi * alpha_hi + s_hi;

#pragma unroll
        for (int nf = 0; nf < 8; nf++) {
            acc_o[nf][0] *= alpha_lo;
            acc_o[nf][1] *= alpha_lo;
            acc_o[nf][2] *= alpha_hi;
            acc_o[nf][3] *= alpha_hi;
        }
        __syncwarp();

        // ---- O += P @ V (raw bits; P truncates, V pre-rounded) ----
        const uint32_t* pw = (const uint32_t*)(Ps + (size_t)(wid * 16) * APP);
#pragma unroll
        for (int kk = 0; kk < 16; kk++) {
            uint32_t pf[4] = {
                pw[(size_t)lq * APP + kk * 8 + lr],
                pw[(size_t)(lq + 8) * APP + kk * 8 + lr],
                pw[(size_t)lq * APP + kk * 8 + lr + 4],
                pw[(size_t)(lq + 8) * APP + kk * 8 + lr + 4]
            };
#pragma unroll
            for (int nf = 0; nf < 8; nf++) {
                uint32_t vf[2] = {
                    V0[(kk * 8 + lr) * AVP + nf * 8 + lq],
                    V0[(kk * 8 + lr + 4) * AVP + nf * 8 + lq]
                };
                mma_tf32(acc_o[nf], pf, vf);
            }
        }
        __syncthreads();
    }

    // ---- normalize + write tf32-rounded to g_o [B,T,C] (gemm1 input) ----
    const float inv_lo = 1.f / l_lo;
    const float inv_hi = 1.f / l_hi;
    float* og_lo = g_o + ((size_t)b * Tn + qt * 128 + r_lo) * Cn + h * Dn;
    float* og_hi = og_lo + 8 * Cn;
#pragma unroll
    for (int nf = 0; nf < 8; nf++) {
        *(float2*)(og_lo + nf * 8 + lr * 2) =
            make_float2(__uint_as_float(f2tf32(acc_o[nf][0] * inv_lo)),
                        __uint_as_float(f2tf32(acc_o[nf][1] * inv_lo)));
        *(float2*)(og_hi + nf * 8 + lr * 2) =
            make_float2(__uint_as_float(f2tf32(acc_o[nf][2] * inv_hi)),
                        __uint_as_float(f2tf32(acc_o[nf][3] * inv_hi)));
    }
#undef LOAD_KV
}

// ---------------------------------------------------------------------------
extern "C" void kernel_launch(void* const* d_in, const int* in_sizes, int n_in,
                              void* d_out, int out_size)
{
    const float* x         = (const float*)d_in[0];
    const float* attn_bias = (const float*)d_in[1];
    const float* qkv_w     = (const float*)d_in[2];
    const float* qkv_b     = (const float*)d_in[3];
    const float* out_w     = (const float*)d_in[4];
    const float* out_b     = (const float*)d_in[5];
    float* out = (float*)d_out;
    (void)in_sizes; (void)n_in; (void)out_size;

    cudaFuncSetAttribute(gemm_mma<0>, cudaFuncAttributeMaxDynamicSharedMemorySize,
                         GEMM_SMEM_BYTES);
    cudaFuncSetAttribute(gemm_mma<1>, cudaFuncAttributeMaxDynamicSharedMemorySize,
                         GEMM_SMEM_BYTES);
    cudaFuncSetAttribute(attn_mma, cudaFuncAttributeMaxDynamicSharedMemorySize,
                         ATTN_SMEM_BYTES);

    // QKV projection (tf32 mma.sync): [8192,1024] @ [3072,1024]^T -> q/k/v scatter
    gemm_mma<0><<<dim3(3072 / 128, 8192 / 128), 256, GEMM_SMEM_BYTES>>>(x, qkv_w, qkv_b, nullptr);

    // Attention (flash, tf32 mma.sync, base-2 online softmax)
    attn_mma<<<dim3(Tn / 128, Hn, Bsz), 256, ATTN_SMEM_BYTES>>>(attn_bias);

    // Output projection (tf32 mma.sync): [8192,1024] @ [1024,1024]^T
    gemm_mma<1><<<dim3(1024 / 128, 8192 / 128), 256, GEMM_SMEM_BYTES>>>(nullptr, out_w, out_b, out);
}

// round 6
// speedup vs baseline: 2.7604x; 1.0606x over previous
#include <cuda_runtime.h>
#include <math.h>
#include <stdint.h>

#define Bsz 4
#define Tn  2048
#define Cn  1024
#define Hn  16
#define Dn  64

// Scratch (static device globals — no allocation allowed)
__device__ float g_q[(size_t)Bsz * Hn * Tn * Dn];   // [B,H,T,D] (tf32-rounded)
__device__ float g_k[(size_t)Bsz * Hn * Tn * Dn];
__device__ float g_v[(size_t)Bsz * Hn * Tn * Dn];
__device__ float g_o[(size_t)Bsz * Tn * Cn];        // [B,T,C]  (tf32-rounded)
__device__ float g_x [(size_t)Bsz * Tn * Cn];       // rna-rounded x
__device__ float g_w0[(size_t)3 * Cn * Cn];         // rna-rounded qkv_w
__device__ float g_w1[(size_t)Cn * Cn];             // rna-rounded out_w

// ---------------------------------------------------------------------------
// helpers
// ---------------------------------------------------------------------------
__device__ __forceinline__ uint32_t smem_u32(const void* p) {
    uint32_t a;
    asm("{ .reg .u64 t; cvta.to.shared.u64 t, %1; cvt.u32.u64 %0, t; }"
        : "=r"(a) : "l"(p));
    return a;
}

__device__ __forceinline__ void cpa16(uint32_t s, const void* g) {
    asm volatile("cp.async.cg.shared.global [%0], [%1], 16;"
                 :: "r"(s), "l"(g) : "memory");
}

__device__ __forceinline__ uint32_t f2tf32(float f) {   // rna round
    uint32_t r;
    asm("cvt.rna.tf32.f32 %0, %1;" : "=r"(r) : "f"(f));
    return r;
}

__device__ __forceinline__ float ex2a(float x) {
    float y;
    asm("ex2.approx.f32 %0, %1;" : "=f"(y) : "f"(x));
    return y;
}

// D += A(16x8) * B(8x8)^T, tf32 (raw fp32 bits; inputs pre-rounded rna), fp32 accum
__device__ __forceinline__ void mma_tf32(float* d, const uint32_t* a, const uint32_t* b) {
    asm volatile(
        "mma.sync.aligned.m16n8k8.row.col.f32.tf32.tf32.f32 "
        "{%0,%1,%2,%3}, {%4,%5,%6,%7}, {%8,%9}, {%0,%1,%2,%3};"
        : "+f"(d[0]), "+f"(d[1]), "+f"(d[2]), "+f"(d[3])
        : "r"(a[0]), "r"(a[1]), "r"(a[2]), "r"(a[3]), "r"(b[0]), "r"(b[1]));
}

// ---------------------------------------------------------------------------
// prepass: rna-round an array to tf32 (dst may equal layout of src), float4-wide
// ---------------------------------------------------------------------------
__global__ __launch_bounds__(256)
void round_tf32(const float* __restrict__ src, float* __restrict__ dst, int n4)
{
    int i = blockIdx.x * 256 + threadIdx.x;
    if (i < n4) {
        float4 v = ((const float4*)src)[i];
        v.x = __uint_as_float(f2tf32(v.x));
        v.y = __uint_as_float(f2tf32(v.y));
        v.z = __uint_as_float(f2tf32(v.z));
        v.w = __uint_as_float(f2tf32(v.w));
        ((float4*)dst)[i] = v;
    }
}

// ---------------------------------------------------------------------------
// tf32 mma.sync GEMM: out[m][n] = sum_k A[m][k] * W[n][k] + bias[n]
// BM=BN=128, BK=32, K=1024, 256 threads (8 warps in 2x4), warp tile 64x32.
// Inputs pre-rounded to tf32 -> raw-bit feeds are exact rna.
// MODE 0: A = g_x, scatter tf32-rounded into g_q/g_k/g_v.  MODE 1: row-major out.
// ---------------------------------------------------------------------------
#define GPAD 36
#define STAGE_FLOATS (2 * 128 * GPAD)
#define GEMM_SMEM_BYTES (2 * STAGE_FLOATS * 4)

template <int MODE>
__global__ __launch_bounds__(256, 2)
void gemm_mma(const float* __restrict__ A, const float* __restrict__ W,
              const float* __restrict__ bias, float* __restrict__ out)
{
    constexpr int KD  = 1024;
    constexpr int NKT = KD / 32;

    extern __shared__ float sm[];
    const uint32_t smb = smem_u32(sm);
    const uint32_t* smu = (const uint32_t*)sm;

    const int tid  = threadIdx.x;
    const int wid  = tid >> 5;
    const int lane = tid & 31;
    const int wm   = wid >> 2;
    const int wn   = wid & 3;
    const int lq   = lane >> 2;
    const int lr   = lane & 3;
    const int n0 = blockIdx.x * 128;
    const int m0 = blockIdx.y * 128;

    const int grow = tid >> 1;
    const int gcb  = (tid & 1) * 16;
    const float* Ag = A + (size_t)(m0 + grow) * KD + gcb;
    const float* Wg = W + (size_t)(n0 + grow) * KD + gcb;
    const uint32_t sArow = (uint32_t)(grow * GPAD + gcb) * 4u;
    const uint32_t sWrow = sArow + 128u * GPAD * 4u;

    int aoff[4], boff[4];
#pragma unroll
    for (int mf = 0; mf < 4; mf++) aoff[mf] = (wm * 64 + mf * 16 + lq) * GPAD + lr;
#pragma unroll
    for (int nf = 0; nf < 4; nf++) boff[nf] = 128 * GPAD + (wn * 32 + nf * 8 + lq) * GPAD + lr;

    float acc[4][4][4];
#pragma unroll
    for (int i = 0; i < 4; i++)
#pragma unroll
        for (int j = 0; j < 4; j++)
#pragma unroll
            for (int e = 0; e < 4; e++) acc[i][j][e] = 0.f;

    {
        uint32_t sb = smb;
#pragma unroll
        for (int j = 0; j < 4; j++) {
            cpa16(sb + sArow + j * 16, Ag + j * 4);
            cpa16(sb + sWrow + j * 16, Wg + j * 4);
        }
        asm volatile("cp.async.commit_group;" ::: "memory");
    }

    for (int t = 0; t < NKT; t++) {
        if (t + 1 < NKT) {
            uint32_t sb = smb + ((t + 1) & 1) * (uint32_t)(STAGE_FLOATS * 4);
            const float* ag = Ag + (t + 1) * 32;
            const float* wg = Wg + (t + 1) * 32;
#pragma unroll
            for (int j = 0; j < 4; j++) {
                cpa16(sb + sArow + j * 16, ag + j * 4);
                cpa16(sb + sWrow + j * 16, wg + j * 4);
            }
            asm volatile("cp.async.commit_group;" ::: "memory");
            asm volatile("cp.async.wait_group 1;" ::: "memory");
        } else {
            asm volatile("cp.async.wait_group 0;" ::: "memory");
        }
        __syncthreads();

        const uint32_t* st = smu + (t & 1) * STAGE_FLOATS;
#pragma unroll
        for (int k0 = 0; k0 < 32; k0 += 8) {
            uint32_t af[4][4], bf[4][2];
#pragma unroll
            for (int mf = 0; mf < 4; mf++) {
                af[mf][0] = st[aoff[mf] + k0];
                af[mf][1] = st[aoff[mf] + 8 * GPAD + k0];
                af[mf][2] = st[aoff[mf] + k0 + 4];
                af[mf][3] = st[aoff[mf] + 8 * GPAD + k0 + 4];
            }
#pragma unroll
            for (int nf = 0; nf < 4; nf++) {
                bf[nf][0] = st[boff[nf] + k0];
                bf[nf][1] = st[boff[nf] + k0 + 4];
            }
#pragma unroll
            for (int mf = 0; mf < 4; mf++)
#pragma unroll
                for (int nf = 0; nf < 4; nf++)
                    mma_tf32(acc[mf][nf], af[mf], bf[nf]);
        }
        __syncthreads();
    }

#pragma unroll
    for (int mf = 0; mf < 4; mf++) {
#pragma unroll
        for (int nf = 0; nf < 4; nf++) {
            const int f0 = n0 + wn * 32 + nf * 8 + lr * 2;
            const int r0 = m0 + wm * 64 + mf * 16 + lq;
            const float b0 = bias[f0], b1 = bias[f0 + 1];
            if (MODE == 0) {
                float2 v0 = make_float2(__uint_as_float(f2tf32(acc[mf][nf][0] + b0)),
                                        __uint_as_float(f2tf32(acc[mf][nf][1] + b1)));
                float2 v1 = make_float2(__uint_as_float(f2tf32(acc[mf][nf][2] + b0)),
                                        __uint_as_float(f2tf32(acc[mf][nf][3] + b1)));
                const int which = f0 >> 10;
                const int fc = f0 & 1023;
                const int hh = fc >> 6;
                const int dd = fc & 63;
                float* dst = (which == 0) ? g_q : (which == 1) ? g_k : g_v;
                const int bb0 = r0 >> 11, tt0 = r0 & 2047;
                const int r1 = r0 + 8;
                const int bb1 = r1 >> 11, tt1 = r1 & 2047;
                *(float2*)(dst + (((size_t)(bb0 * Hn + hh) * Tn + tt0) * Dn + dd)) = v0;
                *(float2*)(dst + (((size_t)(bb1 * Hn + hh) * Tn + tt1) * Dn + dd)) = v1;
            } else {
                float2 v0 = make_float2(acc[mf][nf][0] + b0, acc[mf][nf][1] + b1);
                float2 v1 = make_float2(acc[mf][nf][2] + b0, acc[mf][nf][3] + b1);
                *(float2*)(out + (size_t)r0 * Cn + f0)       = v0;
                *(float2*)(out + (size_t)(r0 + 8) * Cn + f0) = v1;
            }
        }
    }
}

// ---------------------------------------------------------------------------
// Flash attention, tf32 mma.sync. Br=128, Bc=128, D=64, 256 threads (8 warps).
// Warp w owns q-rows w*16..w*16+15 across full N -> softmax stays in-warp.
// P stays in registers: with V k-rows read in permuted order
// sigma(j)=2j (j<4), 2(j-4)+1 (j>=4), the S accumulator IS a valid A-fragment.
// grid: (T/128, H, B)
// ---------------------------------------------------------------------------
#define AKP 68
#define AVP 68
#define A_KSTG (128 * AKP)
#define A_VSTG (128 * AVP)
#define ATTN_SMEM_FLOATS (2 * A_KSTG + 2 * A_VSTG)
#define ATTN_SMEM_BYTES  (ATTN_SMEM_FLOATS * 4)

__global__ __launch_bounds__(256, 1)
void attn_mma(const float* __restrict__ bias)
{
    extern __shared__ float sm[];
    float* Ks = sm;
    float* Vs = sm + 2 * A_KSTG;
    const uint32_t smbK = smem_u32(Ks);
    const uint32_t smbV = smem_u32(Vs);

    const int tid  = threadIdx.x;
    const int wid  = tid >> 5;
    const int lane = tid & 31;
    const int lq   = lane >> 2;
    const int lr   = lane & 3;
    const int qt = blockIdx.x;
    const int h  = blockIdx.y;
    const int b  = blockIdx.z;

    const size_t headoff = ((size_t)(b * Hn + h)) * Tn * Dn;
    const float* qg = g_q + headoff + (size_t)qt * 128 * Dn;
    const float* kg = g_k + headoff;
    const float* vg = g_v + headoff;

    const int r_lo = wid * 16 + lq;
    constexpr float L2E = 1.44269504f;

    // Q fragments in registers, scaled by 1/8*log2(e), rna-rounded once
    uint32_t qf[8][4];
    {
        const float qs = 0.125f * L2E;
#pragma unroll
        for (int ks = 0; ks < 8; ks++) {
            qf[ks][0] = f2tf32(qg[(size_t)r_lo * 64 + ks * 8 + lr] * qs);
            qf[ks][1] = f2tf32(qg[(size_t)(r_lo + 8) * 64 + ks * 8 + lr] * qs);
            qf[ks][2] = f2tf32(qg[(size_t)r_lo * 64 + ks * 8 + lr + 4] * qs);
            qf[ks][3] = f2tf32(qg[(size_t)(r_lo + 8) * 64 + ks * 8 + lr + 4] * qs);
        }
    }

    float m_lo = -1e30f, m_hi = -1e30f, l_lo = 0.f, l_hi = 0.f;
    float acc_o[8][4];
#pragma unroll
    for (int i = 0; i < 8; i++)
#pragma unroll
        for (int e = 0; e < 4; e++) acc_o[i][e] = 0.f;

#define LOAD_KV(KT, STG) do {                                                   \
        const float* kp = kg + (size_t)(KT) * 128 * 64;                         \
        const float* vp = vg + (size_t)(KT) * 128 * 64;                         \
        uint32_t kdst = smbK + (uint32_t)(STG) * (A_KSTG * 4);                  \
        uint32_t vdst = smbV + (uint32_t)(STG) * (A_VSTG * 4);                  \
        _Pragma("unroll")                                                       \
        for (int j = 0; j < 8; j++) {                                           \
            int idx = j * 256 + tid;                                            \
            int row = idx >> 4, c4 = (idx & 15) * 4;                            \
            cpa16(kdst + (uint32_t)(row * AKP + c4) * 4u, kp + row * 64 + c4);  \
            cpa16(vdst + (uint32_t)(row * AVP + c4) * 4u, vp + row * 64 + c4);  \
        }                                                                       \
        asm volatile("cp.async.commit_group;" ::: "memory");                    \
    } while (0)

    LOAD_KV(0, 0);

    const float* bias_lo = bias + ((size_t)b * Tn + qt * 128 + r_lo) * Tn;
    const float* bias_hi = bias_lo + 8 * Tn;

    for (int kt = 0; kt < 16; kt++) {
        if (kt + 1 < 16) {
            LOAD_KV(kt + 1, (kt + 1) & 1);
            asm volatile("cp.async.wait_group 1;" ::: "memory");
        } else {
            asm volatile("cp.async.wait_group 0;" ::: "memory");
        }
        __syncthreads();

        const uint32_t* K0 = (const uint32_t*)(Ks + (kt & 1) * A_KSTG);
        const uint32_t* V0 = (const uint32_t*)(Vs + (kt & 1) * A_VSTG);

        // ---- S = Q @ K^T (raw-bit fragments; all inputs pre-rounded rna) ----
        float acc_s[16][4];
#pragma unroll
        for (int nf = 0; nf < 16; nf++)
#pragma unroll
            for (int e = 0; e < 4; e++) acc_s[nf][e] = 0.f;

#pragma unroll
        for (int nf = 0; nf < 16; nf++) {
            const uint32_t* kr = K0 + (nf * 8 + lq) * AKP;
#pragma unroll
            for (int ks = 0; ks < 8; ks++) {
                uint32_t bf[2] = { kr[ks * 8 + lr], kr[ks * 8 + lr + 4] };
                mma_tf32(acc_s[nf], qf[ks], bf);
            }
        }

        // ---- bias add (x L2E) + row max ----
        float nm_lo = m_lo, nm_hi = m_hi;
#pragma unroll
        for (int nf = 0; nf < 16; nf++) {
            const int c = kt * 128 + nf * 8 + lr * 2;
            float2 b0 = *(const float2*)(bias_lo + c);
            float2 b1 = *(const float2*)(bias_hi + c);
            acc_s[nf][0] = fmaf(b0.x, L2E, acc_s[nf][0]);
            acc_s[nf][1] = fmaf(b0.y, L2E, acc_s[nf][1]);
            acc_s[nf][2] = fmaf(b1.x, L2E, acc_s[nf][2]);
            acc_s[nf][3] = fmaf(b1.y, L2E, acc_s[nf][3]);
            nm_lo = fmaxf(nm_lo, fmaxf(acc_s[nf][0], acc_s[nf][1]));
            nm_hi = fmaxf(nm_hi, fmaxf(acc_s[nf][2], acc_s[nf][3]));
        }
        nm_lo = fmaxf(nm_lo, __shfl_xor_sync(0xffffffffu, nm_lo, 1));
        nm_lo = fmaxf(nm_lo, __shfl_xor_sync(0xffffffffu, nm_lo, 2));
        nm_hi = fmaxf(nm_hi, __shfl_xor_sync(0xffffffffu, nm_hi, 1));
        nm_hi = fmaxf(nm_hi, __shfl_xor_sync(0xffffffffu, nm_hi, 2));

        const float alpha_lo = ex2a(m_lo - nm_lo);
        const float alpha_hi = ex2a(m_hi - nm_hi);
        m_lo = nm_lo; m_hi = nm_hi;

        // ---- exponentiate in-register, rna-round P, partial row sums ----
        float s_lo = 0.f, s_hi = 0.f;
#pragma unroll
        for (int nf = 0; nf < 16; nf++) {
            float p0 = __uint_as_float(f2tf32(ex2a(acc_s[nf][0] - m_lo)));
            float p1 = __uint_as_float(f2tf32(ex2a(acc_s[nf][1] - m_lo)));
            float p2 = __uint_as_float(f2tf32(ex2a(acc_s[nf][2] - m_hi)));
            float p3 = __uint_as_float(f2tf32(ex2a(acc_s[nf][3] - m_hi)));
            s_lo += p0 + p1;
            s_hi += p2 + p3;
            acc_s[nf][0] = p0; acc_s[nf][1] = p1;
            acc_s[nf][2] = p2; acc_s[nf][3] = p3;
        }
        s_lo += __shfl_xor_sync(0xffffffffu, s_lo, 1);
        s_lo += __shfl_xor_sync(0xffffffffu, s_lo, 2);
        s_hi += __shfl_xor_sync(0xffffffffu, s_hi, 1);
        s_hi += __shfl_xor_sync(0xffffffffu, s_hi, 2);
        l_lo = l_lo * alpha_lo + s_lo;
        l_hi = l_hi * alpha_hi + s_hi;

#pragma unroll
        for (int nf = 0; nf < 8; nf++) {
            acc_o[nf][0] *= alpha_lo;
            acc_o[nf][1] *= alpha_lo;
            acc_o[nf][2] *= alpha_hi;
            acc_o[nf][3] *= alpha_hi;
        }

        // ---- O += P @ V, P from registers, V rows sigma-permuted ----
#pragma unroll
        for (int kk = 0; kk < 16; kk++) {
            uint32_t pa[4] = {
                __float_as_uint(acc_s[kk][0]),   // a0 = (lq,   col 2lr)
                __float_as_uint(acc_s[kk][2]),   // a1 = (lq+8, col 2lr)
                __float_as_uint(acc_s[kk][1]),   // a2 = (lq,   col 2lr+1)
                __float_as_uint(acc_s[kk][3])    // a3 = (lq+8, col 2lr+1)
            };
            const uint32_t* vr0 = V0 + (kk * 8 + 2 * lr) * AVP;       // sigma(lr)
            const uint32_t* vr1 = V0 + (kk * 8 + 2 * lr + 1) * AVP;   // sigma(lr+4)
#pragma unroll
            for (int nf = 0; nf < 8; nf++) {
                uint32_t vf[2] = { vr0[nf * 8 + lq], vr1[nf * 8 + lq] };
                mma_tf32(acc_o[nf], pa, vf);
            }
        }
        __syncthreads();
    }

    // ---- normalize + write tf32-rounded to g_o [B,T,C] (gemm1 input) ----
    const float inv_lo = 1.f / l_lo;
    const float inv_hi = 1.f / l_hi;
    float* og_lo = g_o + ((size_t)b * Tn + qt * 128 + r_lo) * Cn + h * Dn;
    float* og_hi = og_lo + 8 * Cn;
#pragma unroll
    for (int nf = 0; nf < 8; nf++) {
        *(float2*)(og_lo + nf * 8 + lr * 2) =
            make_float2(__uint_as_float(f2tf32(acc_o[nf][0] * inv_lo)),
                        __uint_as_float(f2tf32(acc_o[nf][1] * inv_lo)));
        *(float2*)(og_hi + nf * 8 + lr * 2) =
            make_float2(__uint_as_float(f2tf32(acc_o[nf][2] * inv_hi)),
                        __uint_as_float(f2tf32(acc_o[nf][3] * inv_hi)));
    }
#undef LOAD_KV
}

// ---------------------------------------------------------------------------
extern "C" void kernel_launch(void* const* d_in, const int* in_sizes, int n_in,
                              void* d_out, int out_size)
{
    const float* x         = (const float*)d_in[0];
    const float* attn_bias = (const float*)d_in[1];
    const float* qkv_w     = (const float*)d_in[2];
    const float* qkv_b     = (const float*)d_in[3];
    const float* out_w     = (const float*)d_in[4];
    const float* out_b     = (const float*)d_in[5];
    float* out = (float*)d_out;
    (void)in_sizes; (void)n_in; (void)out_size;

    cudaFuncSetAttribute(gemm_mma<0>, cudaFuncAttributeMaxDynamicSharedMemorySize,
                         GEMM_SMEM_BYTES);
    cudaFuncSetAttribute(gemm_mma<1>, cudaFuncAttributeMaxDynamicSharedMemorySize,
                         GEMM_SMEM_BYTES);
    cudaFuncSetAttribute(attn_mma, cudaFuncAttributeMaxDynamicSharedMemorySize,
                         ATTN_SMEM_BYTES);

    float *px, *pw0, *pw1;
    cudaGetSymbolAddress((void**)&px,  g_x);
    cudaGetSymbolAddress((void**)&pw0, g_w0);
    cudaGetSymbolAddress((void**)&pw1, g_w1);

    // prepass: exact-rna tf32 operands for the GEMMs
    {
        int n4x = (Bsz * Tn * Cn) / 4;         // 2,097,152
        int n4w0 = (3 * Cn * Cn) / 4;          //   786,432
        int n4w1 = (Cn * Cn) / 4;              //   262,144
        round_tf32<<<(n4x  + 255) / 256, 256>>>(x,     px,  n4x);
        round_tf32<<<(n4w0 + 255) / 256, 256>>>(qkv_w, pw0, n4w0);
        round_tf32<<<(n4w1 + 255) / 256, 256>>>(out_w, pw1, n4w1);
    }

    // QKV projection (tf32 mma.sync): [8192,1024] @ [3072,1024]^T -> q/k/v scatter
    gemm_mma<0><<<dim3(3072 / 128, 8192 / 128), 256, GEMM_SMEM_BYTES>>>(px, pw0, qkv_b, nullptr);

    // Attention (flash, tf32 mma.sync, P-in-register PV with permuted V rows)
    attn_mma<<<dim3(Tn / 128, Hn, Bsz), 256, ATTN_SMEM_BYTES>>>(attn_bias);

    // Output projection (tf32 mma.sync): [8192,1024] @ [1024,1024]^T
    float* po;
    cudaGetSymbolAddress((void**)&po, g_o);
    gemm_mma<1><<<dim3(1024 / 128, 8192 / 128), 256, GEMM_SMEM_BYTES>>>(po, pw1, out_b, out);
}

// round 7
// speedup vs baseline: 2.7666x; 1.0023x over previous
#include <cuda_runtime.h>
#include <math.h>
#include <stdint.h>

#define Bsz 4
#define Tn  2048
#define Cn  1024
#define Hn  16
#define Dn  64

// Scratch (static device globals — no allocation allowed)
__device__ float g_q[(size_t)Bsz * Hn * Tn * Dn];   // [B,H,T,D] (tf32-rounded)
__device__ float g_k[(size_t)Bsz * Hn * Tn * Dn];
__device__ float g_v[(size_t)Bsz * Hn * Tn * Dn];
__device__ float g_o[(size_t)Bsz * Tn * Cn];        // [B,T,C]  (tf32-rounded)
__device__ float g_x [(size_t)Bsz * Tn * Cn];       // rna-rounded x
__device__ float g_w0[(size_t)3 * Cn * Cn];         // rna-rounded qkv_w
__device__ float g_w1[(size_t)Cn * Cn];             // rna-rounded out_w

// ---------------------------------------------------------------------------
// helpers
// ---------------------------------------------------------------------------
__device__ __forceinline__ uint32_t smem_u32(const void* p) {
    uint32_t a;
    asm("{ .reg .u64 t; cvta.to.shared.u64 t, %1; cvt.u32.u64 %0, t; }"
        : "=r"(a) : "l"(p));
    return a;
}

__device__ __forceinline__ void cpa16(uint32_t s, const void* g) {
    asm volatile("cp.async.cg.shared.global [%0], [%1], 16;"
                 :: "r"(s), "l"(g) : "memory");
}

__device__ __forceinline__ uint32_t f2tf32(float f) {   // rna round
    uint32_t r;
    asm("cvt.rna.tf32.f32 %0, %1;" : "=r"(r) : "f"(f));
    return r;
}

__device__ __forceinline__ float ex2a(float x) {
    float y;
    asm("ex2.approx.f32 %0, %1;" : "=f"(y) : "f"(x));
    return y;
}

// D += A(16x8) * B(8x8)^T, tf32 (raw fp32 bits; inputs pre-rounded rna), fp32 accum
__device__ __forceinline__ void mma_tf32(float* d, const uint32_t* a, const uint32_t* b) {
    asm volatile(
        "mma.sync.aligned.m16n8k8.row.col.f32.tf32.tf32.f32 "
        "{%0,%1,%2,%3}, {%4,%5,%6,%7}, {%8,%9}, {%0,%1,%2,%3};"
        : "+f"(d[0]), "+f"(d[1]), "+f"(d[2]), "+f"(d[3])
        : "r"(a[0]), "r"(a[1]), "r"(a[2]), "r"(a[3]), "r"(b[0]), "r"(b[1]));
}

// ---------------------------------------------------------------------------
// prepass: rna-round an array to tf32, float4-wide
// ---------------------------------------------------------------------------
__global__ __launch_bounds__(256)
void round_tf32(const float* __restrict__ src, float* __restrict__ dst, int n4)
{
    int i = blockIdx.x * 256 + threadIdx.x;
    if (i < n4) {
        float4 v = ((const float4*)src)[i];
        v.x = __uint_as_float(f2tf32(v.x));
        v.y = __uint_as_float(f2tf32(v.y));
        v.z = __uint_as_float(f2tf32(v.z));
        v.w = __uint_as_float(f2tf32(v.w));
        ((float4*)dst)[i] = v;
    }
}

// ---------------------------------------------------------------------------
// tf32 mma.sync GEMM: out[m][n] = sum_k A[m][k] * W[n][k] + bias[n]
// BM=BN=128, BK=32, K=1024, 256 threads (8 warps in 2x4), warp tile 64x32.
// 3-stage cp.async pipeline. Inputs pre-rounded tf32.
// MODE 0: A = g_x, scatter tf32-rounded into g_q/g_k/g_v.  MODE 1: row-major out.
// ---------------------------------------------------------------------------
#define GPAD 36
#define STAGE_FLOATS (2 * 128 * GPAD)
#define GEMM_SMEM_BYTES (3 * STAGE_FLOATS * 4)

template <int MODE>
__global__ __launch_bounds__(256, 2)
void gemm_mma(const float* __restrict__ A, const float* __restrict__ W,
              const float* __restrict__ bias, float* __restrict__ out)
{
    constexpr int KD  = 1024;
    constexpr int NKT = KD / 32;

    extern __shared__ float sm[];
    const uint32_t smb = smem_u32(sm);
    const uint32_t* smu = (const uint32_t*)sm;

    const int tid  = threadIdx.x;
    const int wid  = tid >> 5;
    const int lane = tid & 31;
    const int wm   = wid >> 2;
    const int wn   = wid & 3;
    const int lq   = lane >> 2;
    const int lr   = lane & 3;
    const int n0 = blockIdx.x * 128;
    const int m0 = blockIdx.y * 128;

    const int grow = tid >> 1;
    const int gcb  = (tid & 1) * 16;
    const float* Ag = A + (size_t)(m0 + grow) * KD + gcb;
    const float* Wg = W + (size_t)(n0 + grow) * KD + gcb;
    const uint32_t sArow = (uint32_t)(grow * GPAD + gcb) * 4u;
    const uint32_t sWrow = sArow + 128u * GPAD * 4u;

    int aoff[4], boff[4];
#pragma unroll
    for (int mf = 0; mf < 4; mf++) aoff[mf] = (wm * 64 + mf * 16 + lq) * GPAD + lr;
#pragma unroll
    for (int nf = 0; nf < 4; nf++) boff[nf] = 128 * GPAD + (wn * 32 + nf * 8 + lq) * GPAD + lr;

    float acc[4][4][4];
#pragma unroll
    for (int i = 0; i < 4; i++)
#pragma unroll
        for (int j = 0; j < 4; j++)
#pragma unroll
            for (int e = 0; e < 4; e++) acc[i][j][e] = 0.f;

    // prologue: stages 0 and 1
#pragma unroll
    for (int s = 0; s < 2; s++) {
        uint32_t sb = smb + (uint32_t)s * (STAGE_FLOATS * 4);
        const float* ag = Ag + s * 32;
        const float* wg = Wg + s * 32;
#pragma unroll
        for (int j = 0; j < 4; j++) {
            cpa16(sb + sArow + j * 16, ag + j * 4);
            cpa16(sb + sWrow + j * 16, wg + j * 4);
        }
        asm volatile("cp.async.commit_group;" ::: "memory");
    }

    int stg = 0;       // stage of tile t
    int pstg = 2;      // stage to fill with tile t+2
    for (int t = 0; t < NKT; t++) {
        if (t + 2 < NKT) {
            uint32_t sb = smb + (uint32_t)pstg * (STAGE_FLOATS * 4);
            const float* ag = Ag + (t + 2) * 32;
            const float* wg = Wg + (t + 2) * 32;
#pragma unroll
            for (int j = 0; j < 4; j++) {
                cpa16(sb + sArow + j * 16, ag + j * 4);
                cpa16(sb + sWrow + j * 16, wg + j * 4);
            }
            asm volatile("cp.async.commit_group;" ::: "memory");
            asm volatile("cp.async.wait_group 2;" ::: "memory");
        } else if (t + 1 < NKT) {
            asm volatile("cp.async.wait_group 1;" ::: "memory");
        } else {
            asm volatile("cp.async.wait_group 0;" ::: "memory");
        }
        __syncthreads();

        const uint32_t* st = smu + stg * STAGE_FLOATS;
#pragma unroll
        for (int k0 = 0; k0 < 32; k0 += 8) {
            uint32_t af[4][4], bf[4][2];
#pragma unroll
            for (int mf = 0; mf < 4; mf++) {
                af[mf][0] = st[aoff[mf] + k0];
                af[mf][1] = st[aoff[mf] + 8 * GPAD + k0];
                af[mf][2] = st[aoff[mf] + k0 + 4];
                af[mf][3] = st[aoff[mf] + 8 * GPAD + k0 + 4];
            }
#pragma unroll
            for (int nf = 0; nf < 4; nf++) {
                bf[nf][0] = st[boff[nf] + k0];
                bf[nf][1] = st[boff[nf] + k0 + 4];
            }
#pragma unroll
            for (int mf = 0; mf < 4; mf++)
#pragma unroll
                for (int nf = 0; nf < 4; nf++)
                    mma_tf32(acc[mf][nf], af[mf], bf[nf]);
        }
        __syncthreads();
        stg = (stg == 2) ? 0 : stg + 1;
        pstg = (pstg == 2) ? 0 : pstg + 1;
    }

#pragma unroll
    for (int mf = 0; mf < 4; mf++) {
#pragma unroll
        for (int nf = 0; nf < 4; nf++) {
            const int f0 = n0 + wn * 32 + nf * 8 + lr * 2;
            const int r0 = m0 + wm * 64 + mf * 16 + lq;
            const float b0 = bias[f0], b1 = bias[f0 + 1];
            if (MODE == 0) {
                float2 v0 = make_float2(__uint_as_float(f2tf32(acc[mf][nf][0] + b0)),
                                        __uint_as_float(f2tf32(acc[mf][nf][1] + b1)));
                float2 v1 = make_float2(__uint_as_float(f2tf32(acc[mf][nf][2] + b0)),
                                        __uint_as_float(f2tf32(acc[mf][nf][3] + b1)));
                const int which = f0 >> 10;
                const int fc = f0 & 1023;
                const int hh = fc >> 6;
                const int dd = fc & 63;
                float* dst = (which == 0) ? g_q : (which == 1) ? g_k : g_v;
                const int bb0 = r0 >> 11, tt0 = r0 & 2047;
                const int r1 = r0 + 8;
                const int bb1 = r1 >> 11, tt1 = r1 & 2047;
                *(float2*)(dst + (((size_t)(bb0 * Hn + hh) * Tn + tt0) * Dn + dd)) = v0;
                *(float2*)(dst + (((size_t)(bb1 * Hn + hh) * Tn + tt1) * Dn + dd)) = v1;
            } else {
                float2 v0 = make_float2(acc[mf][nf][0] + b0, acc[mf][nf][1] + b1);
                float2 v1 = make_float2(acc[mf][nf][2] + b0, acc[mf][nf][3] + b1);
                *(float2*)(out + (size_t)r0 * Cn + f0)       = v0;
                *(float2*)(out + (size_t)(r0 + 8) * Cn + f0) = v1;
            }
        }
    }
}

// ---------------------------------------------------------------------------
// Flash attention, tf32 mma.sync. Br=128, Bc=64, D=64, 256 threads (8 warps).
// Warp w owns q-rows w*16..w*16+15 across full Bc -> softmax stays in-warp.
// P stays in registers via sigma-permuted V rows. 2 CTAs/SM.
// grid: (T/128, H, B)
// ---------------------------------------------------------------------------
#define AKP 68
#define AVP 68
#define A_KSTG (64 * AKP)
#define A_VSTG (64 * AVP)
#define ATTN_SMEM_FLOATS (2 * A_KSTG + 2 * A_VSTG)
#define ATTN_SMEM_BYTES  (ATTN_SMEM_FLOATS * 4)

__global__ __launch_bounds__(256, 2)
void attn_mma(const float* __restrict__ bias)
{
    extern __shared__ float sm[];
    float* Ks = sm;
    float* Vs = sm + 2 * A_KSTG;
    const uint32_t smbK = smem_u32(Ks);
    const uint32_t smbV = smem_u32(Vs);

    const int tid  = threadIdx.x;
    const int wid  = tid >> 5;
    const int lane = tid & 31;
    const int lq   = lane >> 2;
    const int lr   = lane & 3;
    const int qt = blockIdx.x;
    const int h  = blockIdx.y;
    const int b  = blockIdx.z;

    const size_t headoff = ((size_t)(b * Hn + h)) * Tn * Dn;
    const float* qg = g_q + headoff + (size_t)qt * 128 * Dn;
    const float* kg = g_k + headoff;
    const float* vg = g_v + headoff;

    const int r_lo = wid * 16 + lq;
    constexpr float L2E = 1.44269504f;

    // Q fragments in registers, scaled by 1/8*log2(e), rna-rounded once
    uint32_t qf[8][4];
    {
        const float qs = 0.125f * L2E;
#pragma unroll
        for (int ks = 0; ks < 8; ks++) {
            qf[ks][0] = f2tf32(qg[(size_t)r_lo * 64 + ks * 8 + lr] * qs);
            qf[ks][1] = f2tf32(qg[(size_t)(r_lo + 8) * 64 + ks * 8 + lr] * qs);
            qf[ks][2] = f2tf32(qg[(size_t)r_lo * 64 + ks * 8 + lr + 4] * qs);
            qf[ks][3] = f2tf32(qg[(size_t)(r_lo + 8) * 64 + ks * 8 + lr + 4] * qs);
        }
    }

    float m_lo = -1e30f, m_hi = -1e30f, l_lo = 0.f, l_hi = 0.f;
    float acc_o[8][4];
#pragma unroll
    for (int i = 0; i < 8; i++)
#pragma unroll
        for (int e = 0; e < 4; e++) acc_o[i][e] = 0.f;

    // 64-row tiles: 1024 float4 each for K and V -> 4 per thread each
#define LOAD_KV(KT, STG) do {                                                   \
        const float* kp = kg + (size_t)(KT) * 64 * 64;                          \
        const float* vp = vg + (size_t)(KT) * 64 * 64;                          \
        uint32_t kdst = smbK + (uint32_t)(STG) * (A_KSTG * 4);                  \
        uint32_t vdst = smbV + (uint32_t)(STG) * (A_VSTG * 4);                  \
        _Pragma("unroll")                                                       \
        for (int j = 0; j < 4; j++) {                                           \
            int idx = j * 256 + tid;                                            \
            int row = idx >> 4, c4 = (idx & 15) * 4;                            \
            cpa16(kdst + (uint32_t)(row * AKP + c4) * 4u, kp + row * 64 + c4);  \
            cpa16(vdst + (uint32_t)(row * AVP + c4) * 4u, vp + row * 64 + c4);  \
        }                                                                       \
        asm volatile("cp.async.commit_group;" ::: "memory");                    \
    } while (0)

    LOAD_KV(0, 0);

    const float* bias_lo = bias + ((size_t)b * Tn + qt * 128 + r_lo) * Tn;
    const float* bias_hi = bias_lo + 8 * Tn;

    for (int kt = 0; kt < 32; kt++) {
        if (kt + 1 < 32) {
            LOAD_KV(kt + 1, (kt + 1) & 1);
            asm volatile("cp.async.wait_group 1;" ::: "memory");
        } else {
            asm volatile("cp.async.wait_group 0;" ::: "memory");
        }
        __syncthreads();

        const uint32_t* K0 = (const uint32_t*)(Ks + (kt & 1) * A_KSTG);
        const uint32_t* V0 = (const uint32_t*)(Vs + (kt & 1) * A_VSTG);

        // ---- S = Q @ K^T over 64 columns ----
        float acc_s[8][4];
#pragma unroll
        for (int nf = 0; nf < 8; nf++)
#pragma unroll
            for (int e = 0; e < 4; e++) acc_s[nf][e] = 0.f;

#pragma unroll
        for (int nf = 0; nf < 8; nf++) {
            const uint32_t* kr = K0 + (nf * 8 + lq) * AKP;
#pragma unroll
            for (int ks = 0; ks < 8; ks++) {
                uint32_t bf[2] = { kr[ks * 8 + lr], kr[ks * 8 + lr + 4] };
                mma_tf32(acc_s[nf], qf[ks], bf);
            }
        }

        // ---- bias add (x L2E) + row max ----
        float nm_lo = m_lo, nm_hi = m_hi;
#pragma unroll
        for (int nf = 0; nf < 8; nf++) {
            const int c = kt * 64 + nf * 8 + lr * 2;
            float2 b0 = *(const float2*)(bias_lo + c);
            float2 b1 = *(const float2*)(bias_hi + c);
            acc_s[nf][0] = fmaf(b0.x, L2E, acc_s[nf][0]);
            acc_s[nf][1] = fmaf(b0.y, L2E, acc_s[nf][1]);
            acc_s[nf][2] = fmaf(b1.x, L2E, acc_s[nf][2]);
            acc_s[nf][3] = fmaf(b1.y, L2E, acc_s[nf][3]);
            nm_lo = fmaxf(nm_lo, fmaxf(acc_s[nf][0], acc_s[nf][1]));
            nm_hi = fmaxf(nm_hi, fmaxf(acc_s[nf][2], acc_s[nf][3]));
        }
        nm_lo = fmaxf(nm_lo, __shfl_xor_sync(0xffffffffu, nm_lo, 1));
        nm_lo = fmaxf(nm_lo, __shfl_xor_sync(0xffffffffu, nm_lo, 2));
        nm_hi = fmaxf(nm_hi, __shfl_xor_sync(0xffffffffu, nm_hi, 1));
        nm_hi = fmaxf(nm_hi, __shfl_xor_sync(0xffffffffu, nm_hi, 2));

        const float alpha_lo = ex2a(m_lo - nm_lo);
        const float alpha_hi = ex2a(m_hi - nm_hi);
        m_lo = nm_lo; m_hi = nm_hi;

        // ---- exponentiate in-register, rna-round P, partial row sums ----
        float s_lo = 0.f, s_hi = 0.f;
#pragma unroll
        for (int nf = 0; nf < 8; nf++) {
            float p0 = __uint_as_float(f2tf32(ex2a(acc_s[nf][0] - m_lo)));
            float p1 = __uint_as_float(f2tf32(ex2a(acc_s[nf][1] - m_lo)));
            float p2 = __uint_as_float(f2tf32(ex2a(acc_s[nf][2] - m_hi)));
            float p3 = __uint_as_float(f2tf32(ex2a(acc_s[nf][3] - m_hi)));
            s_lo += p0 + p1;
            s_hi += p2 + p3;
            acc_s[nf][0] = p0; acc_s[nf][1] = p1;
            acc_s[nf][2] = p2; acc_s[nf][3] = p3;
        }
        s_lo += __shfl_xor_sync(0xffffffffu, s_lo, 1);
        s_lo += __shfl_xor_sync(0xffffffffu, s_lo, 2);
        s_hi += __shfl_xor_sync(0xffffffffu, s_hi, 1);
        s_hi += __shfl_xor_sync(0xffffffffu, s_hi, 2);
        l_lo = l_lo * alpha_lo + s_lo;
        l_hi = l_hi * alpha_hi + s_hi;

#pragma unroll
        for (int nf = 0; nf < 8; nf++) {
            acc_o[nf][0] *= alpha_lo;
            acc_o[nf][1] *= alpha_lo;
            acc_o[nf][2] *= alpha_hi;
            acc_o[nf][3] *= alpha_hi;
        }

        // ---- O += P @ V, P from registers, V rows sigma-permuted ----
#pragma unroll
        for (int kk = 0; kk < 8; kk++) {
            uint32_t pa[4] = {
                __float_as_uint(acc_s[kk][0]),
                __float_as_uint(acc_s[kk][2]),
                __float_as_uint(acc_s[kk][1]),
                __float_as_uint(acc_s[kk][3])
            };
            const uint32_t* vr0 = V0 + (kk * 8 + 2 * lr) * AVP;
            const uint32_t* vr1 = V0 + (kk * 8 + 2 * lr + 1) * AVP;
#pragma unroll
            for (int nf = 0; nf < 8; nf++) {
                uint32_t vf[2] = { vr0[nf * 8 + lq], vr1[nf * 8 + lq] };
                mma_tf32(acc_o[nf], pa, vf);
            }
        }
        __syncthreads();
    }

    // ---- normalize + write tf32-rounded to g_o [B,T,C] (gemm1 input) ----
    const float inv_lo = 1.f / l_lo;
    const float inv_hi = 1.f / l_hi;
    float* og_lo = g_o + ((size_t)b * Tn + qt * 128 + r_lo) * Cn + h * Dn;
    float* og_hi = og_lo + 8 * Cn;
#pragma unroll
    for (int nf = 0; nf < 8; nf++) {
        *(float2*)(og_lo + nf * 8 + lr * 2) =
            make_float2(__uint_as_float(f2tf32(acc_o[nf][0] * inv_lo)),
                        __uint_as_float(f2tf32(acc_o[nf][1] * inv_lo)));
        *(float2*)(og_hi + nf * 8 + lr * 2) =
            make_float2(__uint_as_float(f2tf32(acc_o[nf][2] * inv_hi)),
                        __uint_as_float(f2tf32(acc_o[nf][3] * inv_hi)));
    }
#undef LOAD_KV
}

// ---------------------------------------------------------------------------
extern "C" void kernel_launch(void* const* d_in, const int* in_sizes, int n_in,
                              void* d_out, int out_size)
{
    const float* x         = (const float*)d_in[0];
    const float* attn_bias = (const float*)d_in[1];
    const float* qkv_w     = (const float*)d_in[2];
    const float* qkv_b     = (const float*)d_in[3];
    const float* out_w     = (const float*)d_in[4];
    const float* out_b     = (const float*)d_in[5];
    float* out = (float*)d_out;
    (void)in_sizes; (void)n_in; (void)out_size;

    cudaFuncSetAttribute(gemm_mma<0>, cudaFuncAttributeMaxDynamicSharedMemorySize,
                         GEMM_SMEM_BYTES);
    cudaFuncSetAttribute(gemm_mma<1>, cudaFuncAttributeMaxDynamicSharedMemorySize,
                         GEMM_SMEM_BYTES);
    cudaFuncSetAttribute(attn_mma, cudaFuncAttributeMaxDynamicSharedMemorySize,
                         ATTN_SMEM_BYTES);

    float *px, *pw0, *pw1;
    cudaGetSymbolAddress((void**)&px,  g_x);
    cudaGetSymbolAddress((void**)&pw0, g_w0);
    cudaGetSymbolAddress((void**)&pw1, g_w1);

    // prepass: exact-rna tf32 operands for the GEMMs
    {
        int n4x = (Bsz * Tn * Cn) / 4;
        int n4w0 = (3 * Cn * Cn) / 4;
        int n4w1 = (Cn * Cn) / 4;
        round_tf32<<<(n4x  + 255) / 256, 256>>>(x,     px,  n4x);
        round_tf32<<<(n4w0 + 255) / 256, 256>>>(qkv_w, pw0, n4w0);
        round_tf32<<<(n4w1 + 255) / 256, 256>>>(out_w, pw1, n4w1);
    }

    // QKV projection (tf32 mma.sync): [8192,1024] @ [3072,1024]^T -> q/k/v scatter
    gemm_mma<0><<<dim3(3072 / 128, 8192 / 128), 256, GEMM_SMEM_BYTES>>>(px, pw0, qkv_b, nullptr);

    // Attention (flash, tf32 mma.sync, Bc=64, 2 CTAs/SM)
    attn_mma<<<dim3(Tn / 128, Hn, Bsz), 256, ATTN_SMEM_BYTES>>>(attn_bias);

    // Output projection (tf32 mma.sync): [8192,1024] @ [1024,1024]^T
    float* po;
    cudaGetSymbolAddress((void**)&po, g_o);
    gemm_mma<1><<<dim3(1024 / 128, 8192 / 128), 256, GEMM_SMEM_BYTES>>>(po, pw1, out_b, out);
}

// round 8
// speedup vs baseline: 3.0775x; 1.1124x over previous
#include <cuda_runtime.h>
#include <math.h>
#include <stdint.h>

#define Bsz 4
#define Tn  2048
#define Cn  1024
#define Hn  16
#define Dn  64

// Scratch (static device globals — no allocation allowed)
__device__ float g_q[(size_t)Bsz * Hn * Tn * Dn];   // [B,H,T,D] (tf32-rounded)
__device__ float g_k[(size_t)Bsz * Hn * Tn * Dn];
__device__ float g_v[(size_t)Bsz * Hn * Tn * Dn];
__device__ float g_o[(size_t)Bsz * Tn * Cn];        // [B,T,C]  (tf32-rounded)
__device__ float g_x [(size_t)Bsz * Tn * Cn];       // rna-rounded x
__device__ float g_w0[(size_t)3 * Cn * Cn];         // rna-rounded qkv_w
__device__ float g_w1[(size_t)Cn * Cn];             // rna-rounded out_w

// ---------------------------------------------------------------------------
// helpers
// ---------------------------------------------------------------------------
__device__ __forceinline__ uint32_t smem_u32(const void* p) {
    uint32_t a;
    asm("{ .reg .u64 t; cvta.to.shared.u64 t, %1; cvt.u32.u64 %0, t; }"
        : "=r"(a) : "l"(p));
    return a;
}

__device__ __forceinline__ void cpa16(uint32_t s, const void* g) {
    asm volatile("cp.async.cg.shared.global [%0], [%1], 16;"
                 :: "r"(s), "l"(g) : "memory");
}

__device__ __forceinline__ uint32_t f2tf32(float f) {   // rna round
    uint32_t r;
    asm("cvt.rna.tf32.f32 %0, %1;" : "=r"(r) : "f"(f));
    return r;
}

__device__ __forceinline__ float ex2a(float x) {
    float y;
    asm("ex2.approx.f32 %0, %1;" : "=f"(y) : "f"(x));
    return y;
}

// ldmatrix x4: four 8x8 b16 tiles (used as 8x(16B) row gathers for tf32 frags)
__device__ __forceinline__ void ldsm4(uint32_t* r, uint32_t a) {
    asm volatile("ldmatrix.sync.aligned.m8n8.x4.shared.b16 {%0,%1,%2,%3}, [%4];"
                 : "=r"(r[0]), "=r"(r[1]), "=r"(r[2]), "=r"(r[3]) : "r"(a));
}

// D += A(16x8) * B(8x8)^T, tf32 (raw fp32 bits; inputs pre-rounded rna), fp32 accum
__device__ __forceinline__ void mma_tf32(float* d, const uint32_t* a, const uint32_t* b) {
    asm volatile(
        "mma.sync.aligned.m16n8k8.row.col.f32.tf32.tf32.f32 "
        "{%0,%1,%2,%3}, {%4,%5,%6,%7}, {%8,%9}, {%0,%1,%2,%3};"
        : "+f"(d[0]), "+f"(d[1]), "+f"(d[2]), "+f"(d[3])
        : "r"(a[0]), "r"(a[1]), "r"(a[2]), "r"(a[3]), "r"(b[0]), "r"(b[1]));
}

// ---------------------------------------------------------------------------
// prepass: rna-round an array to tf32, float4-wide
// ---------------------------------------------------------------------------
__global__ __launch_bounds__(256)
void round_tf32(const float* __restrict__ src, float* __restrict__ dst, int n4)
{
    int i = blockIdx.x * 256 + threadIdx.x;
    if (i < n4) {
        float4 v = ((const float4*)src)[i];
        v.x = __uint_as_float(f2tf32(v.x));
        v.y = __uint_as_float(f2tf32(v.y));
        v.z = __uint_as_float(f2tf32(v.z));
        v.w = __uint_as_float(f2tf32(v.w));
        ((float4*)dst)[i] = v;
    }
}

// ---------------------------------------------------------------------------
// tf32 mma.sync GEMM: out[m][n] = sum_k A[m][k] * W[n][k] + bias[n]
// BM=BN=128, BK=32, K=1024, 256 threads (8 warps 2x4), warp tile 64x32.
// 3-stage cp.async, ONE barrier per k-tile, ldmatrix fragment loads.
// MODE 0: A = g_x, scatter tf32-rounded into g_q/g_k/g_v.  MODE 1: row-major out.
// ---------------------------------------------------------------------------
#define GPAD 36
#define STAGE_FLOATS (2 * 128 * GPAD)
#define GEMM_SMEM_BYTES (3 * STAGE_FLOATS * 4)

template <int MODE>
__global__ __launch_bounds__(256, 2)
void gemm_mma(const float* __restrict__ A, const float* __restrict__ W,
              const float* __restrict__ bias, float* __restrict__ out)
{
    constexpr int KD  = 1024;
    constexpr int NKT = KD / 32;

    extern __shared__ float sm[];
    const uint32_t smb = smem_u32(sm);

    const int tid  = threadIdx.x;
    const int wid  = tid >> 5;
    const int lane = tid & 31;
    const int wm   = wid >> 2;
    const int wn   = wid & 3;
    const int lq   = lane >> 2;
    const int lr   = lane & 3;
    const int n0 = blockIdx.x * 128;
    const int m0 = blockIdx.y * 128;

    const int grow = tid >> 1;
    const int gcb  = (tid & 1) * 16;
    const float* Ag = A + (size_t)(m0 + grow) * KD + gcb;
    const float* Wg = W + (size_t)(n0 + grow) * KD + gcb;
    const uint32_t sArow = (uint32_t)(grow * GPAD + gcb) * 4u;
    const uint32_t sWrow = sArow + 128u * GPAD * 4u;

    // ldmatrix per-lane address offsets (bytes, within a stage)
    // A x4: m-halves x k-halves of a 16x8 fragment
    const uint32_t a_off = (uint32_t)((wm * 64 + (lane & 7) + ((lane >> 3) & 1) * 8) * GPAD
                                      + ((lane >> 4) << 2)) * 4u;
    // B x4: one 8-row n-group across 16 k-columns
    const uint32_t b_off = (uint32_t)(128 * GPAD + (wn * 32 + (lane & 7)) * GPAD
                                      + ((lane >> 3) << 2)) * 4u;

    float acc[4][4][4];
#pragma unroll
    for (int i = 0; i < 4; i++)
#pragma unroll
        for (int j = 0; j < 4; j++)
#pragma unroll
            for (int e = 0; e < 4; e++) acc[i][j][e] = 0.f;

    // prologue: stages 0 and 1
#pragma unroll
    for (int s = 0; s < 2; s++) {
        uint32_t sb = smb + (uint32_t)s * (STAGE_FLOATS * 4);
        const float* ag = Ag + s * 32;
        const float* wg = Wg + s * 32;
#pragma unroll
        for (int j = 0; j < 4; j++) {
            cpa16(sb + sArow + j * 16, ag + j * 4);
            cpa16(sb + sWrow + j * 16, wg + j * 4);
        }
        asm volatile("cp.async.commit_group;" ::: "memory");
    }

    int stg = 0;   // stage of tile t
    int pstg = 2;  // stage for tile t+2
    for (int t = 0; t < NKT; t++) {
        if (t + 1 < NKT) asm volatile("cp.async.wait_group 1;" ::: "memory");
        else             asm volatile("cp.async.wait_group 0;" ::: "memory");
        __syncthreads();   // single barrier: stage t visible to all; t-1 reads done

        if (t + 2 < NKT) {
            uint32_t sb = smb + (uint32_t)pstg * (STAGE_FLOATS * 4);
            const float* ag = Ag + (t + 2) * 32;
            const float* wg = Wg + (t + 2) * 32;
#pragma unroll
            for (int j = 0; j < 4; j++) {
                cpa16(sb + sArow + j * 16, ag + j * 4);
                cpa16(sb + sWrow + j * 16, wg + j * 4);
            }
            asm volatile("cp.async.commit_group;" ::: "memory");
        }

        const uint32_t sb = smb + (uint32_t)stg * (STAGE_FLOATS * 4);
#pragma unroll
        for (int h = 0; h < 2; h++) {           // k halves of the BK=32 tile
            uint32_t bfr[4][4];
#pragma unroll
            for (int nf = 0; nf < 4; nf++)
                ldsm4(bfr[nf], sb + b_off + (uint32_t)(nf * 8 * GPAD + h * 16) * 4u);
#pragma unroll
            for (int gg = 0; gg < 2; gg++) {    // k0 = h*16 + gg*8
                uint32_t af[4][4];
#pragma unroll
                for (int mf = 0; mf < 4; mf++)
                    ldsm4(af[mf], sb + a_off
                                  + (uint32_t)(mf * 16 * GPAD + h * 16 + gg * 8) * 4u);
#pragma unroll
                for (int mf = 0; mf < 4; mf++)
#pragma unroll
                    for (int nf = 0; nf < 4; nf++)
                        mma_tf32(acc[mf][nf], af[mf], &bfr[nf][gg * 2]);
            }
        }
        stg = (stg == 2) ? 0 : stg + 1;
        pstg = (pstg == 2) ? 0 : pstg + 1;
    }

#pragma unroll
    for (int mf = 0; mf < 4; mf++) {
#pragma unroll
        for (int nf = 0; nf < 4; nf++) {
            const int f0 = n0 + wn * 32 + nf * 8 + lr * 2;
            const int r0 = m0 + wm * 64 + mf * 16 + lq;
            const float b0 = bias[f0], b1 = bias[f0 + 1];
            if (MODE == 0) {
                float2 v0 = make_float2(__uint_as_float(f2tf32(acc[mf][nf][0] + b0)),
                                        __uint_as_float(f2tf32(acc[mf][nf][1] + b1)));
                float2 v1 = make_float2(__uint_as_float(f2tf32(acc[mf][nf][2] + b0)),
                                        __uint_as_float(f2tf32(acc[mf][nf][3] + b1)));
                const int which = f0 >> 10;
                const int fc = f0 & 1023;
                const int hh = fc >> 6;
                const int dd = fc & 63;
                float* dst = (which == 0) ? g_q : (which == 1) ? g_k : g_v;
                const int bb0 = r0 >> 11, tt0 = r0 & 2047;
                const int r1 = r0 + 8;
                const int bb1 = r1 >> 11, tt1 = r1 & 2047;
                *(float2*)(dst + (((size_t)(bb0 * Hn + hh) * Tn + tt0) * Dn + dd)) = v0;
                *(float2*)(dst + (((size_t)(bb1 * Hn + hh) * Tn + tt1) * Dn + dd)) = v1;
            } else {
                float2 v0 = make_float2(acc[mf][nf][0] + b0, acc[mf][nf][1] + b1);
                float2 v1 = make_float2(acc[mf][nf][2] + b0, acc[mf][nf][3] + b1);
                *(float2*)(out + (size_t)r0 * Cn + f0)       = v0;
                *(float2*)(out + (size_t)(r0 + 8) * Cn + f0) = v1;
            }
        }
    }
}

// ---------------------------------------------------------------------------
// Flash attention, tf32 mma.sync. Br=128, Bc=64, D=64, 256 threads (8 warps).
// 3-stage KV pipeline, ONE barrier per tile, ldmatrix K-fragment loads,
// P kept in registers (sigma-permuted V rows). 2 CTAs/SM.
// grid: (T/128, H, B)
// ---------------------------------------------------------------------------
#define AKP 68
#define AVP 68
#define A_KSTG (64 * AKP)
#define A_VSTG (64 * AVP)
#define ATTN_SMEM_FLOATS (3 * A_KSTG + 3 * A_VSTG)
#define ATTN_SMEM_BYTES  (ATTN_SMEM_FLOATS * 4)

__global__ __launch_bounds__(256, 2)
void attn_mma(const float* __restrict__ bias)
{
    extern __shared__ float sm[];
    float* Ks = sm;                       // 3 x 64 x AKP
    float* Vs = sm + 3 * A_KSTG;          // 3 x 64 x AVP
    const uint32_t smbK = smem_u32(Ks);
    const uint32_t smbV = smem_u32(Vs);

    const int tid  = threadIdx.x;
    const int wid  = tid >> 5;
    const int lane = tid & 31;
    const int lq   = lane >> 2;
    const int lr   = lane & 3;
    const int qt = blockIdx.x;
    const int h  = blockIdx.y;
    const int b  = blockIdx.z;

    const size_t headoff = ((size_t)(b * Hn + h)) * Tn * Dn;
    const float* qg = g_q + headoff + (size_t)qt * 128 * Dn;
    const float* kg = g_k + headoff;
    const float* vg = g_v + headoff;

    const int r_lo = wid * 16 + lq;
    constexpr float L2E = 1.44269504f;

    // K ldmatrix per-lane offset (bytes within a K stage)
    const uint32_t k_off = (uint32_t)((lane & 7) * AKP + ((lane >> 3) << 2)) * 4u;

    // Q fragments in registers, scaled by 1/8*log2(e), rna-rounded once
    uint32_t qf[8][4];
    {
        const float qs = 0.125f * L2E;
#pragma unroll
        for (int ks = 0; ks < 8; ks++) {
            qf[ks][0] = f2tf32(qg[(size_t)r_lo * 64 + ks * 8 + lr] * qs);
            qf[ks][1] = f2tf32(qg[(size_t)(r_lo + 8) * 64 + ks * 8 + lr] * qs);
            qf[ks][2] = f2tf32(qg[(size_t)r_lo * 64 + ks * 8 + lr + 4] * qs);
            qf[ks][3] = f2tf32(qg[(size_t)(r_lo + 8) * 64 + ks * 8 + lr + 4] * qs);
        }
    }

    float m_lo = -1e30f, m_hi = -1e30f, l_lo = 0.f, l_hi = 0.f;
    float acc_o[8][4];
#pragma unroll
    for (int i = 0; i < 8; i++)
#pragma unroll
        for (int e = 0; e < 4; e++) acc_o[i][e] = 0.f;

    // 64-row tiles: 1024 float4 each for K and V -> 4 per thread each
#define LOAD_KV(KT, STG) do {                                                   \
        const float* kp = kg + (size_t)(KT) * 64 * 64;                          \
        const float* vp = vg + (size_t)(KT) * 64 * 64;                          \
        uint32_t kdst = smbK + (uint32_t)(STG) * (A_KSTG * 4);                  \
        uint32_t vdst = smbV + (uint32_t)(STG) * (A_VSTG * 4);                  \
        _Pragma("unroll")                                                       \
        for (int j = 0; j < 4; j++) {                                           \
            int idx = j * 256 + tid;                                            \
            int row = idx >> 4, c4 = (idx & 15) * 4;                            \
            cpa16(kdst + (uint32_t)(row * AKP + c4) * 4u, kp + row * 64 + c4);  \
            cpa16(vdst + (uint32_t)(row * AVP + c4) * 4u, vp + row * 64 + c4);  \
        }                                                                       \
        asm volatile("cp.async.commit_group;" ::: "memory");                    \
    } while (0)

    LOAD_KV(0, 0);
    LOAD_KV(1, 1);

    const float* bias_lo = bias + ((size_t)b * Tn + qt * 128 + r_lo) * Tn;
    const float* bias_hi = bias_lo + 8 * Tn;

    int stg = 0, pstg = 2;
    for (int kt = 0; kt < 32; kt++) {
        if (kt + 1 < 32) asm volatile("cp.async.wait_group 1;" ::: "memory");
        else             asm volatile("cp.async.wait_group 0;" ::: "memory");
        __syncthreads();   // single barrier per tile

        if (kt + 2 < 32) LOAD_KV(kt + 2, pstg);

        const uint32_t Kb = smbK + (uint32_t)stg * (A_KSTG * 4);
        const uint32_t* V0 = (const uint32_t*)(Vs + stg * A_VSTG);

        // ---- S = Q @ K^T over 64 columns (K frags via ldmatrix) ----
        float acc_s[8][4];
#pragma unroll
        for (int nf = 0; nf < 8; nf++)
#pragma unroll
            for (int e = 0; e < 4; e++) acc_s[nf][e] = 0.f;

#pragma unroll
        for (int nf = 0; nf < 8; nf++) {
            uint32_t kb[16];
#pragma unroll
            for (int p = 0; p < 4; p++)
                ldsm4(kb + p * 4, Kb + k_off + (uint32_t)(nf * 8 * AKP + p * 16) * 4u);
#pragma unroll
            for (int ks = 0; ks < 8; ks++)
                mma_tf32(acc_s[nf], qf[ks], kb + (ks >> 1) * 4 + (ks & 1) * 2);
        }

        // ---- bias add (x L2E) + row max ----
        float nm_lo = m_lo, nm_hi = m_hi;
#pragma unroll
        for (int nf = 0; nf < 8; nf++) {
            const int c = kt * 64 + nf * 8 + lr * 2;
            float2 b0 = *(const float2*)(bias_lo + c);
            float2 b1 = *(const float2*)(bias_hi + c);
            acc_s[nf][0] = fmaf(b0.x, L2E, acc_s[nf][0]);
            acc_s[nf][1] = fmaf(b0.y, L2E, acc_s[nf][1]);
            acc_s[nf][2] = fmaf(b1.x, L2E, acc_s[nf][2]);
            acc_s[nf][3] = fmaf(b1.y, L2E, acc_s[nf][3]);
            nm_lo = fmaxf(nm_lo, fmaxf(acc_s[nf][0], acc_s[nf][1]));
            nm_hi = fmaxf(nm_hi, fmaxf(acc_s[nf][2], acc_s[nf][3]));
        }
        nm_lo = fmaxf(nm_lo, __shfl_xor_sync(0xffffffffu, nm_lo, 1));
        nm_lo = fmaxf(nm_lo, __shfl_xor_sync(0xffffffffu, nm_lo, 2));
        nm_hi = fmaxf(nm_hi, __shfl_xor_sync(0xffffffffu, nm_hi, 1));
        nm_hi = fmaxf(nm_hi, __shfl_xor_sync(0xffffffffu, nm_hi, 2));

        const float alpha_lo = ex2a(m_lo - nm_lo);
        const float alpha_hi = ex2a(m_hi - nm_hi);
        m_lo = nm_lo; m_hi = nm_hi;

        // ---- exponentiate in-register, rna-round P, partial row sums ----
        float s_lo = 0.f, s_hi = 0.f;
#pragma unroll
        for (int nf = 0; nf < 8; nf++) {
            float p0 = __uint_as_float(f2tf32(ex2a(acc_s[nf][0] - m_lo)));
            float p1 = __uint_as_float(f2tf32(ex2a(acc_s[nf][1] - m_lo)));
            float p2 = __uint_as_float(f2tf32(ex2a(acc_s[nf][2] - m_hi)));
            float p3 = __uint_as_float(f2tf32(ex2a(acc_s[nf][3] - m_hi)));
            s_lo += p0 + p1;
            s_hi += p2 + p3;
            acc_s[nf][0] = p0; acc_s[nf][1] = p1;
            acc_s[nf][2] = p2; acc_s[nf][3] = p3;
        }
        s_lo += __shfl_xor_sync(0xffffffffu, s_lo, 1);
        s_lo += __shfl_xor_sync(0xffffffffu, s_lo, 2);
        s_hi += __shfl_xor_sync(0xffffffffu, s_hi, 1);
        s_hi += __shfl_xor_sync(0xffffffffu, s_hi, 2);
        l_lo = l_lo * alpha_lo + s_lo;
        l_hi = l_hi * alpha_hi + s_hi;

#pragma unroll
        for (int nf = 0; nf < 8; nf++) {
            acc_o[nf][0] *= alpha_lo;
            acc_o[nf][1] *= alpha_lo;
            acc_o[nf][2] *= alpha_hi;
            acc_o[nf][3] *= alpha_hi;
        }

        // ---- O += P @ V, P from registers, V rows sigma-permuted ----
#pragma unroll
        for (int kk = 0; kk < 8; kk++) {
            uint32_t pa[4] = {
                __float_as_uint(acc_s[kk][0]),
                __float_as_uint(acc_s[kk][2]),
                __float_as_uint(acc_s[kk][1]),
                __float_as_uint(acc_s[kk][3])
            };
            const uint32_t* vr0 = V0 + (kk * 8 + 2 * lr) * AVP;
            const uint32_t* vr1 = V0 + (kk * 8 + 2 * lr + 1) * AVP;
#pragma unroll
            for (int nf = 0; nf < 8; nf++) {
                uint32_t vf[2] = { vr0[nf * 8 + lq], vr1[nf * 8 + lq] };
                mma_tf32(acc_o[nf], pa, vf);
            }
        }
        stg = (stg == 2) ? 0 : stg + 1;
        pstg = (pstg == 2) ? 0 : pstg + 1;
    }

    // ---- normalize + write tf32-rounded to g_o [B,T,C] (gemm1 input) ----
    const float inv_lo = 1.f / l_lo;
    const float inv_hi = 1.f / l_hi;
    float* og_lo = g_o + ((size_t)b * Tn + qt * 128 + r_lo) * Cn + h * Dn;
    float* og_hi = og_lo + 8 * Cn;
#pragma unroll
    for (int nf = 0; nf < 8; nf++) {
        *(float2*)(og_lo + nf * 8 + lr * 2) =
            make_float2(__uint_as_float(f2tf32(acc_o[nf][0] * inv_lo)),
                        __uint_as_float(f2tf32(acc_o[nf][1] * inv_lo)));
        *(float2*)(og_hi + nf * 8 + lr * 2) =
            make_float2(__uint_as_float(f2tf32(acc_o[nf][2] * inv_hi)),
                        __uint_as_float(f2tf32(acc_o[nf][3] * inv_hi)));
    }
#undef LOAD_KV
}

// ---------------------------------------------------------------------------
extern "C" void kernel_launch(void* const* d_in, const int* in_sizes, int n_in,
                              void* d_out, int out_size)
{
    const float* x         = (const float*)d_in[0];
    const float* attn_bias = (const float*)d_in[1];
    const float* qkv_w     = (const float*)d_in[2];
    const float* qkv_b     = (const float*)d_in[3];
    const float* out_w     = (const float*)d_in[4];
    const float* out_b     = (const float*)d_in[5];
    float* out = (float*)d_out;
    (void)in_sizes; (void)n_in; (void)out_size;

    cudaFuncSetAttribute(gemm_mma<0>, cudaFuncAttributeMaxDynamicSharedMemorySize,
                         GEMM_SMEM_BYTES);
    cudaFuncSetAttribute(gemm_mma<1>, cudaFuncAttributeMaxDynamicSharedMemorySize,
                         GEMM_SMEM_BYTES);
    cudaFuncSetAttribute(attn_mma, cudaFuncAttributeMaxDynamicSharedMemorySize,
                         ATTN_SMEM_BYTES);

    float *px, *pw0, *pw1;
    cudaGetSymbolAddress((void**)&px,  g_x);
    cudaGetSymbolAddress((void**)&pw0, g_w0);
    cudaGetSymbolAddress((void**)&pw1, g_w1);

    // prepass: exact-rna tf32 operands for the GEMMs
    {
        int n4x = (Bsz * Tn * Cn) / 4;
        int n4w0 = (3 * Cn * Cn) / 4;
        int n4w1 = (Cn * Cn) / 4;
        round_tf32<<<(n4x  + 255) / 256, 256>>>(x,     px,  n4x);
        round_tf32<<<(n4w0 + 255) / 256, 256>>>(qkv_w, pw0, n4w0);
        round_tf32<<<(n4w1 + 255) / 256, 256>>>(out_w, pw1, n4w1);
    }

    // QKV projection (tf32 mma.sync): [8192,1024] @ [3072,1024]^T -> q/k/v scatter
    gemm_mma<0><<<dim3(3072 / 128, 8192 / 128), 256, GEMM_SMEM_BYTES>>>(px, pw0, qkv_b, nullptr);

    // Attention (flash, tf32 mma.sync, Bc=64, 3-stage, ldmatrix K)
    attn_mma<<<dim3(Tn / 128, Hn, Bsz), 256, ATTN_SMEM_BYTES>>>(attn_bias);

    // Output projection (tf32 mma.sync): [8192,1024] @ [1024,1024]^T
    float* po;
    cudaGetSymbolAddress((void**)&po, g_o);
    gemm_mma<1><<<dim3(1024 / 128, 8192 / 128), 256, GEMM_SMEM_BYTES>>>(po, pw1, out_b, out);
}

// round 9
// speedup vs baseline: 6.2046x; 2.0161x over previous
#include <cuda_runtime.h>
#include <cuda_fp16.h>
#include <math.h>
#include <stdint.h>

#define Bsz 4
#define Tn  2048
#define Cn  1024
#define Hn  16
#define Dn  64

// Scratch (static device globals — no allocation allowed)
__device__ __half g_q[(size_t)Bsz * Hn * Tn * Dn];   // [B,H,T,D], pre-scaled by 0.125*log2e
__device__ __half g_k[(size_t)Bsz * Hn * Tn * Dn];
__device__ __half g_v[(size_t)Bsz * Hn * Tn * Dn];
__device__ __half g_o[(size_t)Bsz * Tn * Cn];        // [B,T,C] attention out (fp16)
__device__ __half g_x [(size_t)Bsz * Tn * Cn];       // x  -> fp16
__device__ __half g_w0[(size_t)3 * Cn * Cn];         // qkv_w -> fp16
__device__ __half g_w1[(size_t)Cn * Cn];             // out_w -> fp16

// ---------------------------------------------------------------------------
// helpers
// ---------------------------------------------------------------------------
__device__ __forceinline__ uint32_t smem_u32(const void* p) {
    uint32_t a;
    asm("{ .reg .u64 t; cvta.to.shared.u64 t, %1; cvt.u32.u64 %0, t; }"
        : "=r"(a) : "l"(p));
    return a;
}

__device__ __forceinline__ void cpa16(uint32_t s, const void* g) {
    asm volatile("cp.async.cg.shared.global [%0], [%1], 16;"
                 :: "r"(s), "l"(g) : "memory");
}

__device__ __forceinline__ float ex2a(float x) {
    float y;
    asm("ex2.approx.f32 %0, %1;" : "=f"(y) : "f"(x));
    return y;
}

// pack two f32 -> f16x2 (lo, hi), round-to-nearest
__device__ __forceinline__ uint32_t pack_h2(float lo, float hi) {
    uint32_t r;
    asm("cvt.rn.f16x2.f32 %0, %1, %2;" : "=r"(r) : "f"(hi), "f"(lo));
    return r;
}

__device__ __forceinline__ void ldsm4(uint32_t* r, uint32_t a) {
    asm volatile("ldmatrix.sync.aligned.m8n8.x4.shared.b16 {%0,%1,%2,%3}, [%4];"
                 : "=r"(r[0]), "=r"(r[1]), "=r"(r[2]), "=r"(r[3]) : "r"(a));
}

__device__ __forceinline__ void ldsm4t(uint32_t* r, uint32_t a) {
    asm volatile("ldmatrix.sync.aligned.m8n8.x4.trans.shared.b16 {%0,%1,%2,%3}, [%4];"
                 : "=r"(r[0]), "=r"(r[1]), "=r"(r[2]), "=r"(r[3]) : "r"(a));
}

// D += A(16x16) * B(8x16)^T, fp16 inputs, fp32 accum
__device__ __forceinline__ void mma_f16(float* d, const uint32_t* a, const uint32_t* b) {
    asm volatile(
        "mma.sync.aligned.m16n8k16.row.col.f32.f16.f16.f32 "
        "{%0,%1,%2,%3}, {%4,%5,%6,%7}, {%8,%9}, {%0,%1,%2,%3};"
        : "+f"(d[0]), "+f"(d[1]), "+f"(d[2]), "+f"(d[3])
        : "r"(a[0]), "r"(a[1]), "r"(a[2]), "r"(a[3]), "r"(b[0]), "r"(b[1]));
}

// ---------------------------------------------------------------------------
// prepass: round fp32 array to fp16 (rn), 4 elems/thread
// ---------------------------------------------------------------------------
__global__ __launch_bounds__(256)
void round_f16(const float* __restrict__ src, __half* __restrict__ dst, int n4)
{
    int i = blockIdx.x * 256 + threadIdx.x;
    if (i < n4) {
        float4 v = ((const float4*)src)[i];
        uint2 o;
        o.x = pack_h2(v.x, v.y);
        o.y = pack_h2(v.z, v.w);
        *(uint2*)(dst + (size_t)i * 4) = o;
    }
}

// ---------------------------------------------------------------------------
// fp16 mma.sync GEMM: out[m][n] = sum_k A[m][k]*W[n][k] + bias[n]
// BM=BN=128, BK=32, K=1024, 256 threads (8 warps 2x4), warp tile 64x32.
// 3-stage cp.async, one barrier per k-tile, ldmatrix fragments.
// MODE 0: scatter fp16 into g_q (scaled)/g_k/g_v.  MODE 1: fp32 row-major out.
// ---------------------------------------------------------------------------
#define GPADH 40                                  // halfs per row (32 data + 8 pad)
#define G_TILE_B (128 * GPADH * 2)                // 10240 B (one operand)
#define G_STAGE_B (2 * G_TILE_B)                  // A + B
#define GEMM_SMEM_BYTES (3 * G_STAGE_B)

template <int MODE>
__global__ __launch_bounds__(256, 2)
void gemm_mma(const __half* __restrict__ A, const __half* __restrict__ W,
              const float* __restrict__ bias, float* __restrict__ out)
{
    constexpr int KD  = 1024;
    constexpr int NKT = KD / 32;
    constexpr float QS = 0.125f * 1.44269504f;

    extern __shared__ char sm[];
    const uint32_t smb = smem_u32(sm);

    const int tid  = threadIdx.x;
    const int wid  = tid >> 5;
    const int lane = tid & 31;
    const int wm   = wid >> 2;
    const int wn   = wid & 3;
    const int lq   = lane >> 2;
    const int lr   = lane & 3;
    const int n0 = blockIdx.x * 128;
    const int m0 = blockIdx.y * 128;

    // ldmatrix lane-offsets (bytes within stage)
    const uint32_t a_off = (uint32_t)((wm * 64 + (lane & 7) + ((lane >> 3) & 1) * 8) * (GPADH * 2)
                                      + ((lane >> 4) & 1) * 16);
    const uint32_t b_off = (uint32_t)G_TILE_B
                         + (uint32_t)((wn * 32 + ((lane >> 4) & 1) * 8 + (lane & 7)) * (GPADH * 2)
                                      + ((lane >> 3) & 1) * 16);

    float acc[4][4][4];
#pragma unroll
    for (int i = 0; i < 4; i++)
#pragma unroll
        for (int j = 0; j < 4; j++)
#pragma unroll
            for (int e = 0; e < 4; e++) acc[i][j][e] = 0.f;

    // loader: A and W tiles, 128 rows x 32 halfs (4 x 16B per row), 2 chunks/thread each
#define G_LOAD(T, SB) do {                                                        \
        _Pragma("unroll")                                                         \
        for (int j = 0; j < 2; j++) {                                             \
            int c = j * 256 + tid;                                                \
            int row = c >> 2, c4 = c & 3;                                         \
            cpa16((SB) + (uint32_t)(row * (GPADH * 2) + c4 * 16),                 \
                  A + (size_t)(m0 + row) * KD + (T) * 32 + c4 * 8);               \
            cpa16((SB) + (uint32_t)G_TILE_B + (uint32_t)(row * (GPADH * 2) + c4 * 16), \
                  W + (size_t)(n0 + row) * KD + (T) * 32 + c4 * 8);               \
        }                                                                         \
        asm volatile("cp.async.commit_group;" ::: "memory");                      \
    } while (0)

    G_LOAD(0, smb);
    G_LOAD(1, smb + G_STAGE_B);

    int stg = 0, pstg = 2;
    for (int t = 0; t < NKT; t++) {
        if (t + 1 < NKT) asm volatile("cp.async.wait_group 1;" ::: "memory");
        else             asm volatile("cp.async.wait_group 0;" ::: "memory");
        __syncthreads();

        if (t + 2 < NKT) G_LOAD(t + 2, smb + (uint32_t)pstg * G_STAGE_B);

        const uint32_t sb = smb + (uint32_t)stg * G_STAGE_B;
#pragma unroll
        for (int kc = 0; kc < 2; kc++) {       // two k16 steps in BK=32
            uint32_t bf[2][4];                 // [n-pair][regs]
#pragma unroll
            for (int np = 0; np < 2; np++)
                ldsm4(bf[np], sb + b_off + (uint32_t)(np * 16 * (GPADH * 2) + kc * 32));
            uint32_t af[4][4];
#pragma unroll
            for (int mf = 0; mf < 4; mf++)
                ldsm4(af[mf], sb + a_off + (uint32_t)(mf * 16 * (GPADH * 2) + kc * 32));
#pragma unroll
            for (int mf = 0; mf < 4; mf++)
#pragma unroll
                for (int nf = 0; nf < 4; nf++)
                    mma_f16(acc[mf][nf], af[mf], &bf[nf >> 1][(nf & 1) * 2]);
        }
        stg = (stg == 2) ? 0 : stg + 1;
        pstg = (pstg == 2) ? 0 : pstg + 1;
    }
#undef G_LOAD

#pragma unroll
    for (int mf = 0; mf < 4; mf++) {
#pragma unroll
        for (int nf = 0; nf < 4; nf++) {
            const int f0 = n0 + wn * 32 + nf * 8 + lr * 2;
            const int r0 = m0 + wm * 64 + mf * 16 + lq;
            const float b0 = bias[f0], b1 = bias[f0 + 1];
            float e00 = acc[mf][nf][0] + b0, e01 = acc[mf][nf][1] + b1;
            float e10 = acc[mf][nf][2] + b0, e11 = acc[mf][nf][3] + b1;
            if (MODE == 0) {
                const int which = f0 >> 10;
                if (which == 0) { e00 *= QS; e01 *= QS; e10 *= QS; e11 *= QS; }
                const int fc = f0 & 1023;
                const int hh = fc >> 6;
                const int dd = fc & 63;
                __half* dst = (which == 0) ? g_q : (which == 1) ? g_k : g_v;
                const int bb0 = r0 >> 11, tt0 = r0 & 2047;
                const int r1 = r0 + 8;
                const int bb1 = r1 >> 11, tt1 = r1 & 2047;
                *(uint32_t*)(dst + (((size_t)(bb0 * Hn + hh) * Tn + tt0) * Dn + dd)) =
                    pack_h2(e00, e01);
                *(uint32_t*)(dst + (((size_t)(bb1 * Hn + hh) * Tn + tt1) * Dn + dd)) =
                    pack_h2(e10, e11);
            } else {
                *(float2*)(out + (size_t)r0 * Cn + f0)       = make_float2(e00, e01);
                *(float2*)(out + (size_t)(r0 + 8) * Cn + f0) = make_float2(e10, e11);
            }
        }
    }
}

// ---------------------------------------------------------------------------
// Flash attention, fp16 mma.sync m16n8k16. Br=128, Bc=64, 256 threads (8 warps).
// Warp w owns q-rows w*16..+15; softmax in-warp; P packed from S accumulators;
// V fragments via ldmatrix.trans. 3-stage KV pipeline, 2 CTAs/SM.
// grid: (T/128, H, B)
// ---------------------------------------------------------------------------
#define KVPADH 72                                  // halfs per row (64 + 8 pad)
#define KV_TILE_B (64 * KVPADH * 2)                // 9216 B
#define ATTN_SMEM_BYTES (6 * KV_TILE_B)            // 3 stages x (K + V)

__global__ __launch_bounds__(256, 2)
void attn_mma(const float* __restrict__ bias)
{
    extern __shared__ char sm[];
    const uint32_t smbK = smem_u32(sm);
    const uint32_t smbV = smbK + 3 * KV_TILE_B;

    const int tid  = threadIdx.x;
    const int wid  = tid >> 5;
    const int lane = tid & 31;
    const int lq   = lane >> 2;
    const int lr   = lane & 3;
    const int qt = blockIdx.x;
    const int h  = blockIdx.y;
    const int b  = blockIdx.z;

    const size_t headoff = ((size_t)(b * Hn + h)) * Tn * Dn;
    const __half* qg = g_q + headoff + (size_t)qt * 128 * Dn;
    const __half* kg = g_k + headoff;
    const __half* vg = g_v + headoff;

    const int r_lo = wid * 16 + lq;
    constexpr float L2E = 1.44269504f;

    // ldmatrix lane offsets (bytes within a tile)
    const uint32_t k_off = (uint32_t)((((lane >> 4) & 1) * 8 + (lane & 7)) * (KVPADH * 2)
                                      + ((lane >> 3) & 1) * 16);
    const uint32_t v_off = (uint32_t)(((lane & 7) + ((lane >> 3) & 1) * 8) * (KVPADH * 2)
                                      + ((lane >> 4) & 1) * 16);

    // Q a-frags (already scaled by 0.125*log2e at gemm0 epilogue), 4 k16 chunks
    uint32_t qf[4][4];
#pragma unroll
    for (int kc = 0; kc < 4; kc++) {
        qf[kc][0] = *(const uint32_t*)(qg + (size_t)r_lo * 64 + kc * 16 + 2 * lr);
        qf[kc][1] = *(const uint32_t*)(qg + (size_t)(r_lo + 8) * 64 + kc * 16 + 2 * lr);
        qf[kc][2] = *(const uint32_t*)(qg + (size_t)r_lo * 64 + kc * 16 + 2 * lr + 8);
        qf[kc][3] = *(const uint32_t*)(qg + (size_t)(r_lo + 8) * 64 + kc * 16 + 2 * lr + 8);
    }

    float m_lo = -1e30f, m_hi = -1e30f, l_lo = 0.f, l_hi = 0.f;
    float acc_o[8][4];
#pragma unroll
    for (int i = 0; i < 8; i++)
#pragma unroll
        for (int e = 0; e < 4; e++) acc_o[i][e] = 0.f;

    // K/V tile loader: 64 rows x 64 halfs each = 512 chunks of 16B -> 2/thread each
#define LOAD_KV(KT, STG) do {                                                    \
        const __half* kp = kg + (size_t)(KT) * 64 * 64;                          \
        const __half* vp = vg + (size_t)(KT) * 64 * 64;                          \
        uint32_t kdst = smbK + (uint32_t)(STG) * KV_TILE_B;                      \
        uint32_t vdst = smbV + (uint32_t)(STG) * KV_TILE_B;                      \
        _Pragma("unroll")                                                        \
        for (int j = 0; j < 2; j++) {                                            \
            int c = j * 256 + tid;                                               \
            int row = c >> 3, c8 = c & 7;                                        \
            uint32_t so = (uint32_t)(row * (KVPADH * 2) + c8 * 16);              \
            cpa16(kdst + so, kp + row * 64 + c8 * 8);                            \
            cpa16(vdst + so, vp + row * 64 + c8 * 8);                            \
        }                                                                        \
        asm volatile("cp.async.commit_group;" ::: "memory");                     \
    } while (0)

    LOAD_KV(0, 0);
    LOAD_KV(1, 1);

    const float* bias_lo = bias + ((size_t)b * Tn + qt * 128 + r_lo) * Tn;
    const float* bias_hi = bias_lo + 8 * Tn;

    int stg = 0, pstg = 2;
    for (int kt = 0; kt < 32; kt++) {
        if (kt + 1 < 32) asm volatile("cp.async.wait_group 1;" ::: "memory");
        else             asm volatile("cp.async.wait_group 0;" ::: "memory");
        __syncthreads();

        if (kt + 2 < 32) LOAD_KV(kt + 2, pstg);

        const uint32_t Kb = smbK + (uint32_t)stg * KV_TILE_B;
        const uint32_t Vb = smbV + (uint32_t)stg * KV_TILE_B;

        // ---- S = Q @ K^T : 8 seq n-groups (4 pairs) x 4 k16 ----
        float acc_s[8][4];
#pragma unroll
        for (int nf = 0; nf < 8; nf++)
#pragma unroll
            for (int e = 0; e < 4; e++) acc_s[nf][e] = 0.f;

#pragma unroll
        for (int np = 0; np < 4; np++) {
#pragma unroll
            for (int kc = 0; kc < 4; kc++) {
                uint32_t kb[4];
                ldsm4(kb, Kb + k_off + (uint32_t)(np * 16 * (KVPADH * 2) + kc * 32));
                mma_f16(acc_s[np * 2],     qf[kc], kb);
                mma_f16(acc_s[np * 2 + 1], qf[kc], kb + 2);
            }
        }

        // ---- bias add (x L2E) + row max ----
        float nm_lo = m_lo, nm_hi = m_hi;
#pragma unroll
        for (int nf = 0; nf < 8; nf++) {
            const int c = kt * 64 + nf * 8 + lr * 2;
            float2 b0 = *(const float2*)(bias_lo + c);
            float2 b1 = *(const float2*)(bias_hi + c);
            acc_s[nf][0] = fmaf(b0.x, L2E, acc_s[nf][0]);
            acc_s[nf][1] = fmaf(b0.y, L2E, acc_s[nf][1]);
            acc_s[nf][2] = fmaf(b1.x, L2E, acc_s[nf][2]);
            acc_s[nf][3] = fmaf(b1.y, L2E, acc_s[nf][3]);
            nm_lo = fmaxf(nm_lo, fmaxf(acc_s[nf][0], acc_s[nf][1]));
            nm_hi = fmaxf(nm_hi, fmaxf(acc_s[nf][2], acc_s[nf][3]));
        }
        nm_lo = fmaxf(nm_lo, __shfl_xor_sync(0xffffffffu, nm_lo, 1));
        nm_lo = fmaxf(nm_lo, __shfl_xor_sync(0xffffffffu, nm_lo, 2));
        nm_hi = fmaxf(nm_hi, __shfl_xor_sync(0xffffffffu, nm_hi, 1));
        nm_hi = fmaxf(nm_hi, __shfl_xor_sync(0xffffffffu, nm_hi, 2));

        const float alpha_lo = ex2a(m_lo - nm_lo);
        const float alpha_hi = ex2a(m_hi - nm_hi);
        m_lo = nm_lo; m_hi = nm_hi;

        // ---- exponentiate + partial sums ----
        float s_lo = 0.f, s_hi = 0.f;
#pragma unroll
        for (int nf = 0; nf < 8; nf++) {
            float p0 = ex2a(acc_s[nf][0] - m_lo);
            float p1 = ex2a(acc_s[nf][1] - m_lo);
            float p2 = ex2a(acc_s[nf][2] - m_hi);
            float p3 = ex2a(acc_s[nf][3] - m_hi);
            s_lo += p0 + p1;
            s_hi += p2 + p3;
            acc_s[nf][0] = p0; acc_s[nf][1] = p1;
            acc_s[nf][2] = p2; acc_s[nf][3] = p3;
        }
        s_lo += __shfl_xor_sync(0xffffffffu, s_lo, 1);
        s_lo += __shfl_xor_sync(0xffffffffu, s_lo, 2);
        s_hi += __shfl_xor_sync(0xffffffffu, s_hi, 1);
        s_hi += __shfl_xor_sync(0xffffffffu, s_hi, 2);
        l_lo = l_lo * alpha_lo + s_lo;
        l_hi = l_hi * alpha_hi + s_hi;

#pragma unroll
        for (int nf = 0; nf < 8; nf++) {
            acc_o[nf][0] *= alpha_lo;
            acc_o[nf][1] *= alpha_lo;
            acc_o[nf][2] *= alpha_hi;
            acc_o[nf][3] *= alpha_hi;
        }

        // ---- O += P @ V : 4 k16 steps x 8 d n-groups (4 pairs), V via ldsm.trans ----
#pragma unroll
        for (int kk = 0; kk < 4; kk++) {
            uint32_t pa[4] = {
                pack_h2(acc_s[2 * kk][0],     acc_s[2 * kk][1]),
                pack_h2(acc_s[2 * kk][2],     acc_s[2 * kk][3]),
                pack_h2(acc_s[2 * kk + 1][0], acc_s[2 * kk + 1][1]),
                pack_h2(acc_s[2 * kk + 1][2], acc_s[2 * kk + 1][3])
            };
#pragma unroll
            for (int dp = 0; dp < 4; dp++) {
                uint32_t vb[4];
                ldsm4t(vb, Vb + v_off + (uint32_t)(kk * 16 * (KVPADH * 2) + dp * 32));
                mma_f16(acc_o[dp * 2],     pa, vb);
                mma_f16(acc_o[dp * 2 + 1], pa, vb + 2);
            }
        }
        stg = (stg == 2) ? 0 : stg + 1;
        pstg = (pstg == 2) ? 0 : pstg + 1;
    }
#undef LOAD_KV

    // ---- normalize + write fp16 to g_o [B,T,C] (gemm1 input) ----
    const float inv_lo = 1.f / l_lo;
    const float inv_hi = 1.f / l_hi;
    __half* og_lo = g_o + ((size_t)b * Tn + qt * 128 + r_lo) * Cn + h * Dn;
    __half* og_hi = og_lo + 8 * Cn;
#pragma unroll
    for (int nf = 0; nf < 8; nf++) {
        *(uint32_t*)(og_lo + nf * 8 + lr * 2) =
            pack_h2(acc_o[nf][0] * inv_lo, acc_o[nf][1] * inv_lo);
        *(uint32_t*)(og_hi + nf * 8 + lr * 2) =
            pack_h2(acc_o[nf][2] * inv_hi, acc_o[nf][3] * inv_hi);
    }
}

// ---------------------------------------------------------------------------
extern "C" void kernel_launch(void* const* d_in, const int* in_sizes, int n_in,
                              void* d_out, int out_size)
{
    const float* x         = (const float*)d_in[0];
    const float* attn_bias = (const float*)d_in[1];
    const float* qkv_w     = (const float*)d_in[2];
    const float* qkv_b     = (const float*)d_in[3];
    const float* out_w     = (const float*)d_in[4];
    const float* out_b     = (const float*)d_in[5];
    float* out = (float*)d_out;
    (void)in_sizes; (void)n_in; (void)out_size;

    cudaFuncSetAttribute(gemm_mma<0>, cudaFuncAttributeMaxDynamicSharedMemorySize,
                         GEMM_SMEM_BYTES);
    cudaFuncSetAttribute(gemm_mma<1>, cudaFuncAttributeMaxDynamicSharedMemorySize,
                         GEMM_SMEM_BYTES);
    cudaFuncSetAttribute(attn_mma, cudaFuncAttributeMaxDynamicSharedMemorySize,
                         ATTN_SMEM_BYTES);

    __half *px, *pw0, *pw1, *po;
    cudaGetSymbolAddress((void**)&px,  g_x);
    cudaGetSymbolAddress((void**)&pw0, g_w0);
    cudaGetSymbolAddress((void**)&pw1, g_w1);
    cudaGetSymbolAddress((void**)&po,  g_o);

    // prepass: fp16(rn) GEMM operands
    {
        int n4x  = (Bsz * Tn * Cn) / 4;
        int n4w0 = (3 * Cn * Cn) / 4;
        int n4w1 = (Cn * Cn) / 4;
        round_f16<<<(n4x  + 255) / 256, 256>>>(x,     px,  n4x);
        round_f16<<<(n4w0 + 255) / 256, 256>>>(qkv_w, pw0, n4w0);
        round_f16<<<(n4w1 + 255) / 256, 256>>>(out_w, pw1, n4w1);
    }

    // QKV projection (fp16 mma.sync): [8192,1024] @ [3072,1024]^T -> q/k/v scatter
    gemm_mma<0><<<dim3(3072 / 128, 8192 / 128), 256, GEMM_SMEM_BYTES>>>(px, pw0, qkv_b, nullptr);

    // Attention (flash, fp16 m16n8k16, base-2 online softmax)
    attn_mma<<<dim3(Tn / 128, Hn, Bsz), 256, ATTN_SMEM_BYTES>>>(attn_bias);

    // Output projection (fp16 mma.sync): [8192,1024] @ [1024,1024]^T -> fp32 out
    gemm_mma<1><<<dim3(1024 / 128, 8192 / 128), 256, GEMM_SMEM_BYTES>>>(po, pw1, out_b, out);
}